// round 6
// baseline (speedup 1.0000x reference)
#include <cuda_runtime.h>
#include <cuda_fp16.h>
#include <stdint.h>

#define D 128
#define DPAD 132

static __device__ float g_A [46792704];
static __device__ float g_B [46792704];
static __device__ float g_C [46792704];
static __device__ float g_A2[ 2752512];
static __device__ float g_B2[ 2752512];
static __device__ float g_C2[ 2752512];
static __device__ float g_acc [18*256];
static __device__ float g_fold[19*256];
static __device__ float g_wT  [884736];
static __device__ uint4 g_wf4 [49152];

__global__ void init_kernel(float* acc, float* foldId) {
    int t = blockIdx.x * blockDim.x + threadIdx.x;
    if (t < 18*256) acc[t] = 0.f;
    if (t < 128) { foldId[t] = 1.f; foldId[128 + t] = 0.f; }
}

__global__ void transpose_kernel(const float* __restrict__ src, float* __restrict__ dst,
                                 int R, int C, int total) {
    int idx = blockIdx.x * blockDim.x + threadIdx.x;
    if (idx >= total) return;
    int m = idx / (R * C), rc = idx - m * (R * C), cc = rc / R, r = rc - cc * R;
    dst[idx] = src[m * R * C + r * C + cc];
}

// pack W[outN][K] fp32 -> PAIRED m16n8k16 B-fragments (uint4 = two adjacent n-tiles)
__global__ void prep_frag(const float* __restrict__ W, uint4* __restrict__ out,
                          int NT, int K, int total) {
    int idx = blockIdx.x * blockDim.x + threadIdx.x;
    if (idx >= total) return;
    int lane = idx & 31, q = idx >> 5;
    int g = lane >> 2, t = lane & 3;
    uint32_t r[4];
    #pragma unroll
    for (int s = 0; s < 2; ++s) {
        int tile = 2*q + s, nt = tile % NT, kt = tile / NT;
        const float* w = W + (size_t)(nt * 8 + g) * K + kt * 16 + 2 * t;
        __half2 b0 = __floats2half2_rn(w[0], w[1]);
        __half2 b1 = __floats2half2_rn(w[8], w[9]);
        r[2*s]   = *(uint32_t*)&b0;
        r[2*s+1] = *(uint32_t*)&b1;
    }
    uint4 o; o.x = r[0]; o.y = r[1]; o.z = r[2]; o.w = r[3];
    out[idx] = o;
}

__global__ void embed_kernel(const float* __restrict__ poses, const float* __restrict__ ew,
                             const float* __restrict__ eb, float* __restrict__ out, int total) {
    int idx = blockIdx.x * blockDim.x + threadIdx.x;
    if (idx >= total) return;
    int row = idx >> 7, c = idx & 127;
    float v = fmaf(poses[row*2], ew[2*c], fmaf(poses[row*2+1], ew[2*c+1], eb[c]));
    out[idx] = v > 0.f ? v : 0.01f * v;
}

__global__ void finalize_kernel(const float* __restrict__ acc, float invN,
                                const float* g0, const float* b0, float* f0,
                                const float* g1, const float* b1, float* f1) {
    int set = blockIdx.x, c = threadIdx.x;
    const float* a  = acc + set * 256;
    const float* gg = set ? g1 : g0;
    const float* bb = set ? b1 : b0;
    float* ff = set ? f1 : f0;
    float m = a[c] * invN;
    float v = fmaxf(a[128 + c] * invN - m * m, 0.f);
    float sc = rsqrtf(v + 1e-5f) * gg[c];
    ff[c] = sc;
    ff[128 + c] = fmaf(-m, sc, bb[c]);
}

__global__ void pool1_kernel(const float* __restrict__ hin, const float* __restrict__ fold,
                             float* __restrict__ out, int total) {
    int idx = blockIdx.x * blockDim.x + threadIdx.x;
    if (idx >= total) return;
    int orow = idx >> 7, c = idx & 127;
    const float* base = hin + (size_t)orow * 17 * D + c;
    float s = 0.f;
    #pragma unroll
    for (int j = 0; j < 17; ++j) s += base[j * D];
    out[idx] = fmaf(s * (1.f / 17.f), fold[c], fold[128 + c]);
}

__global__ void pool2_cls_kernel(const float* __restrict__ hin, const float* __restrict__ fold,
                                 const float* __restrict__ cw, const float* __restrict__ cb,
                                 float* __restrict__ out) {
    __shared__ float p_s[D];
    int b = blockIdx.x, c = threadIdx.x;
    const float* base = hin + (size_t)b * 84 * D + c;
    float s = 0.f;
    #pragma unroll 4
    for (int r = 0; r < 84; ++r) s += base[r * D];
    p_s[c] = fmaf(s * (1.f / 84.f), fold[c], fold[128 + c]);
    __syncthreads();
    if (c < 8) {
        float acc = cb[c];
        #pragma unroll 4
        for (int k = 0; k < D; ++k) acc = fmaf(p_s[k], cw[c * D + k], acc);
        out[b * 8 + c] = acc;
    }
}

__device__ __forceinline__ void mma16816(float* c, uint32_t a0, uint32_t a1,
                                         uint32_t a2, uint32_t a3, uint32_t b0, uint32_t b1) {
    asm("mma.sync.aligned.m16n8k16.row.col.f32.f16.f16.f32 "
        "{%0,%1,%2,%3},{%4,%5,%6,%7},{%8,%9},{%0,%1,%2,%3};"
        : "+f"(c[0]), "+f"(c[1]), "+f"(c[2]), "+f"(c[3])
        : "r"(a0), "r"(a1), "r"(a2), "r"(a3), "r"(b0), "r"(b1));
}

// A via ldmatrix.x4 (rows must be 16B-aligned: lda*2 % 16 == 0), B via uint4 pairs
template<int KT, int NT>
__device__ __forceinline__ void mtile(const __half* a_tile, int lda, const uint4* __restrict__ wf,
                                      int ng, int lane, float acc[4][4]) {
    uint32_t sbase = (uint32_t)__cvta_generic_to_shared(a_tile)
                   + (uint32_t)((lane & 15) * lda * 2) + ((lane >> 4) & 1) * 16;
    #pragma unroll
    for (int kt = 0; kt < KT; ++kt) {
        uint32_t a0, a1, a2, a3;
        asm volatile("ldmatrix.sync.aligned.m8n8.x4.shared.b16 {%0,%1,%2,%3}, [%4];"
                     : "=r"(a0), "=r"(a1), "=r"(a2), "=r"(a3) : "r"(sbase + kt*32));
        #pragma unroll
        for (int jj = 0; jj < 2; ++jj) {
            uint4 b = wf[(((kt*NT + ng*4) >> 1) + jj)*32 + lane];
            mma16816(acc[2*jj],   a0, a1, a2, a3, b.x, b.y);
            mma16816(acc[2*jj+1], a0, a1, a2, a3, b.z, b.w);
        }
    }
}

// ---------------- stage-1 tensor kernels: 4 graphs (68 rows), 512 threads --
#define O_H16 0
#define O_Q16 21760
#define O_K16 43520
#define O_VT  65280
#define O_P   100096
#define O_SC  134912
#define O_MB  162112
#define SM1   166208

__global__ __launch_bounds__(512)
void k1_s1(const float* __restrict__ hin, const float* __restrict__ foldIn,
           float* __restrict__ t1, float* __restrict__ t2, float* __restrict__ accL,
           const float* __restrict__ gwT, const float* __restrict__ gb,
           const float* __restrict__ qb, const float* __restrict__ ob,
           const uint4* __restrict__ qkvf, const uint4* __restrict__ owf) {
    extern __shared__ char sm[];
    __half (*h16)[136] = (__half(*)[136])(sm + O_H16);
    __half (*q16)[136] = (__half(*)[136])(sm + O_Q16);
    __half (*k16)[136] = (__half(*)[136])(sm + O_K16);
    __half (*vT )[34]  = (__half(*)[34]) (sm + O_VT);   // [4*128][34]
    __half (*pp )[34]  = (__half(*)[34]) (sm + O_P);    // [4*4*32][34]
    float  (*sc )[25]  = (float(*)[25])  (sm + O_SC);   // [272][25]
    float*  mbuf       = (float*)(sm + O_MB);           // 1024 floats

    const int tid = threadIdx.x, warp = tid >> 5, lane = tid & 31;
    const int g = lane >> 2, t = lane & 3;
    const int colj = tid & 127;
    const float* hg = hin + (size_t)blockIdx.x * 8704;
    float* t1g = t1 + (size_t)blockIdx.x * 8704;
    float* t2g = t2 + (size_t)blockIdx.x * 8704;
    const float scIn = foldIn[colj], shIn = foldIn[128 + colj];

    { // zero vT+pp (contiguous 69632B) and h16 pad rows, load h16 = half(BN(h))
        uint32_t* z = (uint32_t*)(sm + O_VT);
        for (int i = tid; i < 17408; i += 512) z[i] = 0;
        uint32_t* zh = (uint32_t*)&h16[68][0];
        for (int i = tid; i < 816; i += 512) zh[i] = 0;
        for (int i = tid; i < 8704; i += 512)
            h16[i >> 7][colj] = __float2half_rn(fmaf(hg[i], scIn, shIn));
    }
    __syncthreads();
    { // per-graph mean
        int gi = tid >> 7, cc = tid & 127;
        float s = 0.f;
        #pragma unroll
        for (int r = 0; r < 17; ++r) s += __half2float(h16[gi*17 + r][cc]);
        mbuf[tid] = s * (1.f / 17.f);
    }
    __syncthreads();
    { // GCN rank-1
        int gi = tid >> 7, cc = tid & 127;
        float a = gb[cc];
        const float* mrow = mbuf + gi * 128;
        #pragma unroll 4
        for (int k = 0; k < 128; ++k) a = fmaf(mrow[k], gwT[k*128 + cc], a);
        mbuf[512 + tid] = a;
    }
    __syncthreads();
    { // t1 = gcn + BN(h), stats
        float s1 = 0.f, q1 = 0.f;
        for (int i = tid; i < 8704; i += 512) {
            int rr = i >> 7;
            float v = mbuf[512 + (rr/17)*128 + colj] + fmaf(hg[i], scIn, shIn);
            t1g[i] = v; s1 += v; q1 = fmaf(v, v, q1);
        }
        float* red = (float*)sc;
        red[tid] = s1; red[512 + tid] = q1;
    }
    __syncthreads();
    if (tid < 128) {
        float* red = (float*)sc;
        atomicAdd(&accL[tid],       red[tid] + red[tid+128] + red[tid+256] + red[tid+384]);
        atomicAdd(&accL[128 + tid], red[512+tid] + red[640+tid] + red[768+tid] + red[896+tid]);
    }
    // qkv: M=80, N=384, K=128
    for (int item = warp; item < 60; item += 16) {
        int mt = item / 12, ng = item % 12, m0 = mt * 16;
        float acc[4][4] = {};
        mtile<8,48>(&h16[m0][0], 136, qkvf, ng, lane, acc);
        int r0 = m0 + g, r1 = r0 + 8;
        #pragma unroll
        for (int j = 0; j < 4; ++j) {
            int nc = ng*32 + j*8 + 2*t;
            float b0 = qb[nc], b1 = qb[nc+1];
            float v00 = acc[j][0]+b0, v01 = acc[j][1]+b1, v10 = acc[j][2]+b0, v11 = acc[j][3]+b1;
            if (nc < 128) {
                *(__half2*)&q16[r0][nc] = __floats2half2_rn(v00, v01);
                *(__half2*)&q16[r1][nc] = __floats2half2_rn(v10, v11);
            } else if (nc < 256) {
                *(__half2*)&k16[r0][nc-128] = __floats2half2_rn(v00, v01);
                *(__half2*)&k16[r1][nc-128] = __floats2half2_rn(v10, v11);
            } else {
                int d = nc - 256;
                if (r0 < 68) { int gi = r0/17, sl = r0 - gi*17;
                    vT[gi*128+d][sl] = __float2half_rn(v00); vT[gi*128+d+1][sl] = __float2half_rn(v01); }
                if (r1 < 68) { int gi = r1/17, sl = r1 - gi*17;
                    vT[gi*128+d][sl] = __float2half_rn(v10); vT[gi*128+d+1][sl] = __float2half_rn(v11); }
            }
        }
    }
    __syncthreads();
    // scores
    for (int item = warp; item < 96; item += 16) {
        int gi = item / 24, r = item % 24, hh = r / 6, r2 = r % 6, mt = r2 / 3, nt = r2 % 3;
        int base = gi * 17;
        float acc[4] = {};
        const __half* a0p = &q16[base + mt*16 + g][hh*32 + 2*t];
        const __half* a1p = a0p + 8*136;
        const __half* br  = &k16[base + nt*8 + g][hh*32 + 2*t];
        #pragma unroll
        for (int kt = 0; kt < 2; ++kt) {
            mma16816(acc, *(const uint32_t*)(a0p+kt*16), *(const uint32_t*)(a1p+kt*16),
                     *(const uint32_t*)(a0p+kt*16+8), *(const uint32_t*)(a1p+kt*16+8),
                     *(const uint32_t*)(br+kt*16), *(const uint32_t*)(br+kt*16+8));
        }
        const float invs = 0.17677669529663687f;
        int q0 = mt*16 + g, ss = nt*8 + 2*t, row = (gi*4 + hh)*17;
        if (q0 < 17)     { sc[row+q0][ss]   = acc[0]*invs; sc[row+q0][ss+1]   = acc[1]*invs; }
        if (q0 + 8 < 17) { sc[row+q0+8][ss] = acc[2]*invs; sc[row+q0+8][ss+1] = acc[3]*invs; }
    }
    __syncthreads();
    for (int idx = tid; idx < 272; idx += 512) { // softmax -> fp16 probs
        int gh = idx / 17, q = idx - gh*17;
        float e[17], mx = -1e30f;
        #pragma unroll
        for (int s = 0; s < 17; ++s) mx = fmaxf(mx, sc[gh*17+q][s]);
        float sum = 0.f;
        #pragma unroll
        for (int s = 0; s < 17; ++s) { e[s] = __expf(sc[gh*17+q][s] - mx); sum += e[s]; }
        float inv = 1.f / sum;
        #pragma unroll
        for (int s = 0; s < 17; ++s) pp[gh*32 + q][s] = __float2half_rn(e[s] * inv);
    }
    __syncthreads();
    // attn @ V -> q16 (reuse); pp/vT rows are 68B so keep scalar LDS path here
    for (int item = warp; item < 32; item += 16) {
        int gi = item / 8, r = item % 8, hh = r / 2, mt = r % 2;
        float acc[4][4] = {};
        const __half* a0p = &pp[(gi*4+hh)*32 + mt*16 + g][2*t];
        const __half* a1p = a0p + 8*34;
        #pragma unroll
        for (int kt = 0; kt < 2; ++kt) {
            uint32_t a0 = *(const uint32_t*)(a0p+kt*16), a1 = *(const uint32_t*)(a1p+kt*16);
            uint32_t a2 = *(const uint32_t*)(a0p+kt*16+8), a3 = *(const uint32_t*)(a1p+kt*16+8);
            #pragma unroll
            for (int j = 0; j < 4; ++j) {
                const __half* bp = &vT[gi*128 + hh*32 + j*8 + g][kt*16 + 2*t];
                mma16816(acc[j], a0, a1, a2, a3, *(const uint32_t*)bp, *(const uint32_t*)(bp+8));
            }
        }
        int q0 = mt*16 + g;
        #pragma unroll
        for (int j = 0; j < 4; ++j) {
            int col = hh*32 + j*8 + 2*t;
            if (q0 < 17)     *(__half2*)&q16[gi*17+q0][col]   = __floats2half2_rn(acc[j][0], acc[j][1]);
            if (q0 + 8 < 17) *(__half2*)&q16[gi*17+q0+8][col] = __floats2half2_rn(acc[j][2], acc[j][3]);
        }
    }
    __syncthreads();
    // out-proj + residual -> t2
    for (int item = warp; item < 20; item += 16) {
        int mt = item / 4, ng = item % 4, m0 = mt * 16;
        float acc[4][4] = {};
        mtile<8,16>(&q16[m0][0], 136, owf, ng, lane, acc);
        int r0 = m0 + g, r1 = r0 + 8;
        #pragma unroll
        for (int j = 0; j < 4; ++j) {
            int nc = ng*32 + j*8 + 2*t;
            float b0 = ob[nc], b1 = ob[nc+1];
            float f0 = foldIn[nc], f0s = foldIn[128+nc], f1 = foldIn[nc+1], f1s = foldIn[129+nc];
            if (r0 < 68) {
                t2g[r0*128+nc]   = acc[j][0] + b0 + fmaf(hg[r0*128+nc],   f0, f0s);
                t2g[r0*128+nc+1] = acc[j][1] + b1 + fmaf(hg[r0*128+nc+1], f1, f1s);
            }
            if (r1 < 68) {
                t2g[r1*128+nc]   = acc[j][2] + b0 + fmaf(hg[r1*128+nc],   f0, f0s);
                t2g[r1*128+nc+1] = acc[j][3] + b1 + fmaf(hg[r1*128+nc+1], f1, f1s);
            }
        }
    }
    __syncthreads();
    { // t2 stats
        float s2 = 0.f, q2 = 0.f;
        for (int i = tid; i < 8704; i += 512) {
            float v = t2g[i]; s2 += v; q2 = fmaf(v, v, q2);
        }
        mbuf[tid] = s2; mbuf[512 + tid] = q2;
        __syncthreads();
        if (tid < 128) {
            atomicAdd(&accL[256 + tid], mbuf[tid] + mbuf[tid+128] + mbuf[tid+256] + mbuf[tid+384]);
            atomicAdd(&accL[384 + tid], mbuf[512+tid] + mbuf[640+tid] + mbuf[768+tid] + mbuf[896+tid]);
        }
    }
}

#define SM2 (39168 + 76032)
__global__ __launch_bounds__(512)
void k2_s1(const float* __restrict__ t1, const float* __restrict__ t2,
           const float* __restrict__ fold1, const float* __restrict__ fold2,
           float* __restrict__ hout, float* __restrict__ accL,
           const uint4* __restrict__ w1f, const float* __restrict__ b1v,
           const uint4* __restrict__ w2f, const float* __restrict__ b2v) {
    extern __shared__ char sm[];
    __half (*o16)[136] = (__half(*)[136])(sm);          // [144][136]
    __half (*u16)[264] = (__half(*)[264])(sm + 39168);  // [144][264]
    const int tid = threadIdx.x, warp = tid >> 5, lane = tid & 31;
    const int g = lane >> 2, t = lane & 3;
    const int colj = tid & 127;
    const float* t1g = t1 + (size_t)blockIdx.x * 17408;
    const float* t2g = t2 + (size_t)blockIdx.x * 17408;
    float* og = hout + (size_t)blockIdx.x * 17408;
    const float sc1 = fold1[colj], sh1 = fold1[128 + colj];
    const float sc2 = fold2[colj], sh2 = fold2[128 + colj];

    for (int i = tid; i < 17408; i += 512)
        o16[i >> 7][colj] = __float2half_rn(fmaf(t1g[i], sc1, sh1) + fmaf(t2g[i], sc2, sh2));
    { // zero pad rows 136-143
        uint32_t* zz = (uint32_t*)&o16[136][0];
        for (int i = tid; i < 544; i += 512) zz[i] = 0;
    }
    __syncthreads();
    // mlp1: M=144, N=256, K=128 (+ReLU)
    for (int item = warp; item < 72; item += 16) {
        int mt = item / 8, ng = item % 8, m0 = mt * 16;
        float acc[4][4] = {};
        mtile<8,32>(&o16[m0][0], 136, w1f, ng, lane, acc);
        int r0 = m0 + g, r1 = r0 + 8;
        #pragma unroll
        for (int j = 0; j < 4; ++j) {
            int nc = ng*32 + j*8 + 2*t;
            float b0 = b1v[nc], b1 = b1v[nc+1];
            *(__half2*)&u16[r0][nc] = __floats2half2_rn(fmaxf(acc[j][0]+b0, 0.f), fmaxf(acc[j][1]+b1, 0.f));
            *(__half2*)&u16[r1][nc] = __floats2half2_rn(fmaxf(acc[j][2]+b0, 0.f), fmaxf(acc[j][3]+b1, 0.f));
        }
    }
    __syncthreads();
    // mlp2: M=144, N=128, K=256 + residual
    for (int item = warp; item < 36; item += 16) {
        int mt = item / 4, ng = item % 4, m0 = mt * 16;
        float acc[4][4] = {};
        mtile<16,16>(&u16[m0][0], 264, w2f, ng, lane, acc);
        int r0 = m0 + g, r1 = r0 + 8;
        #pragma unroll
        for (int j = 0; j < 4; ++j) {
            int nc = ng*32 + j*8 + 2*t;
            float b0 = b2v[nc], b1 = b2v[nc+1];
            float fa = fold1[nc], fas = fold1[128+nc], fb = fold2[nc], fbs = fold2[128+nc];
            float fa1 = fold1[nc+1], fas1 = fold1[129+nc], fb1 = fold2[nc+1], fbs1 = fold2[129+nc];
            if (r0 < 136) {
                int i0 = r0*128+nc;
                og[i0]   = acc[j][0] + b0 + fmaf(t1g[i0],   fa,  fas)  + fmaf(t2g[i0],   fb,  fbs);
                og[i0+1] = acc[j][1] + b1 + fmaf(t1g[i0+1], fa1, fas1) + fmaf(t2g[i0+1], fb1, fbs1);
            }
            if (r1 < 136) {
                int i1 = r1*128+nc;
                og[i1]   = acc[j][2] + b0 + fmaf(t1g[i1],   fa,  fas)  + fmaf(t2g[i1],   fb,  fbs);
                og[i1+1] = acc[j][3] + b1 + fmaf(t1g[i1+1], fa1, fas1) + fmaf(t2g[i1+1], fb1, fbs1);
            }
        }
    }
    __syncthreads();
    {
        float s3 = 0.f, q3 = 0.f;
        for (int i = tid; i < 17408; i += 512) {
            float v = og[i]; s3 += v; q3 = fmaf(v, v, q3);
        }
        float* red = (float*)u16;
        red[tid] = s3; red[512 + tid] = q3;
        __syncthreads();
        if (tid < 128) {
            atomicAdd(&accL[tid],       red[tid] + red[tid+128] + red[tid+256] + red[tid+384]);
            atomicAdd(&accL[128 + tid], red[512+tid] + red[640+tid] + red[768+tid] + red[896+tid]);
        }
    }
}

// ---------------- stage-2 scalar path (proven) -----------------------------
template<int N>
__device__ __forceinline__ void gemm128(const float (*hs)[DPAD], const float* __restrict__ wT,
                                        int ldw, int cidx, float bias, float* out) {
    #pragma unroll
    for (int r = 0; r < N; ++r) out[r] = bias;
    #pragma unroll 2
    for (int k = 0; k < D; k += 4) {
        float w0 = wT[(k+0)*ldw + cidx], w1 = wT[(k+1)*ldw + cidx];
        float w2 = wT[(k+2)*ldw + cidx], w3 = wT[(k+3)*ldw + cidx];
        #pragma unroll
        for (int r = 0; r < N; ++r) {
            float4 hv = *reinterpret_cast<const float4*>(&hs[r][k]);
            out[r] = fmaf(hv.x, w0, out[r]); out[r] = fmaf(hv.y, w1, out[r]);
            out[r] = fmaf(hv.z, w2, out[r]); out[r] = fmaf(hv.w, w3, out[r]);
        }
    }
}

template<int N, int GPB>
__global__ __launch_bounds__(128)
void k1_kernel(const float* __restrict__ hin, const float* __restrict__ foldIn,
               float* __restrict__ t1, float* __restrict__ t2, float* __restrict__ acc,
               const float* __restrict__ gwT, const float* __restrict__ gb,
               const float* __restrict__ qwT, const float* __restrict__ qb,
               const float* __restrict__ owT, const float* __restrict__ ob) {
    __shared__ float h_s[N][DPAD], q_s[N][DPAD], k_s[N][DPAD], v_s[N][DPAD];
    __shared__ float sc_s[4][N][N + 1], m_s[D];
    const int c = threadIdx.x, wp = c >> 5, lane = c & 31;
    const float scIn = foldIn[c], shIn = foldIn[D + c];
    const float gbv = gb[c], obv = ob[c];
    const float qbq = qb[c], qbk = qb[D + c], qbv = qb[2*D + c];
    float s1 = 0.f, sq1 = 0.f, s2 = 0.f, sq2 = 0.f;
    for (int gi = 0; gi < GPB; ++gi) {
        const int g = blockIdx.x * GPB + gi;
        const float* hg = hin + (size_t)g * (N * D);
        float mv = 0.f;
        #pragma unroll
        for (int r = 0; r < N; ++r) {
            float v = fmaf(hg[r*D + c], scIn, shIn);
            h_s[r][c] = v; mv += v;
        }
        m_s[c] = mv * (1.f / N);
        __syncthreads();
        float gcnv = gbv;
        #pragma unroll 4
        for (int k = 0; k < D; ++k) gcnv = fmaf(m_s[k], gwT[k*D + c], gcnv);
        {
            float* t1g = t1 + (size_t)g * (N * D);
            #pragma unroll
            for (int r = 0; r < N; ++r) {
                float v = gcnv + h_s[r][c];
                t1g[r*D + c] = v; s1 += v; sq1 = fmaf(v, v, sq1);
            }
        }
        {
            float a[N];
            gemm128<N>(h_s, qwT, 384, c, qbq, a);
            #pragma unroll
            for (int r = 0; r < N; ++r) q_s[r][c] = a[r];
            gemm128<N>(h_s, qwT, 384, c + 128, qbk, a);
            #pragma unroll
            for (int r = 0; r < N; ++r) k_s[r][c] = a[r];
            gemm128<N>(h_s, qwT, 384, c + 256, qbv, a);
            #pragma unroll
            for (int r = 0; r < N; ++r) v_s[r][c] = a[r];
        }
        __syncthreads();
        {
            const float invs = 0.17677669529663687f;
            for (int p = lane; p < N * N; p += 32) {
                int r = p / N, s = p - r * N;
                float d0 = 0.f;
                #pragma unroll
                for (int d = 0; d < 32; d += 4) {
                    float4 qq = *reinterpret_cast<const float4*>(&q_s[r][wp*32 + d]);
                    float4 kk = *reinterpret_cast<const float4*>(&k_s[s][wp*32 + d]);
                    d0 = fmaf(qq.x, kk.x, d0); d0 = fmaf(qq.y, kk.y, d0);
                    d0 = fmaf(qq.z, kk.z, d0); d0 = fmaf(qq.w, kk.w, d0);
                }
                sc_s[wp][r][s] = d0 * invs;
            }
            __syncwarp();
            if (lane < N) {
                float mx = -1e30f;
                #pragma unroll
                for (int s = 0; s < N; ++s) mx = fmaxf(mx, sc_s[wp][lane][s]);
                float sum = 0.f;
                #pragma unroll
                for (int s = 0; s < N; ++s) { float e = __expf(sc_s[wp][lane][s] - mx); sc_s[wp][lane][s] = e; sum += e; }
                float inv = 1.f / sum;
                #pragma unroll
                for (int s = 0; s < N; ++s) sc_s[wp][lane][s] *= inv;
            }
            __syncwarp();
            #pragma unroll
            for (int r = 0; r < N; ++r) {
                float o = 0.f;
                #pragma unroll
                for (int s = 0; s < N; ++s) o = fmaf(sc_s[wp][r][s], v_s[s][wp*32 + lane], o);
                q_s[r][wp*32 + lane] = o;
            }
        }
        __syncthreads();
        {
            float a[N];
            gemm128<N>(q_s, owT, 128, c, obv, a);
            float* t2g = t2 + (size_t)g * (N * D);
            #pragma unroll
            for (int r = 0; r < N; ++r) {
                float v = a[r] + h_s[r][c];
                t2g[r*D + c] = v; s2 += v; sq2 = fmaf(v, v, sq2);
            }
        }
        __syncthreads();
    }
    atomicAdd(&acc[c], s1); atomicAdd(&acc[128 + c], sq1);
    atomicAdd(&acc[256 + c], s2); atomicAdd(&acc[384 + c], sq2);
}

template<int N, int GPB>
__global__ __launch_bounds__(128)
void k2_kernel(const float* __restrict__ t1, const float* __restrict__ t2,
               const float* __restrict__ fold1, const float* __restrict__ fold2,
               float* __restrict__ hout, float* __restrict__ acc,
               const float* __restrict__ w1T, const float* __restrict__ b1,
               const float* __restrict__ w2T, const float* __restrict__ b2) {
    __shared__ float o_s[N][DPAD], u_s[N][260];
    const int c = threadIdx.x;
    const float sc1 = fold1[c], sh1 = fold1[128 + c];
    const float sc2 = fold2[c], sh2 = fold2[128 + c];
    const float b1a = b1[c], b1b = b1[128 + c], b2a = b2[c];
    float s3 = 0.f, q3 = 0.f;
    for (int gi = 0; gi < GPB; ++gi) {
        const int g = blockIdx.x * GPB + gi;
        const float* t1g = t1 + (size_t)g * (N * D);
        const float* t2g = t2 + (size_t)g * (N * D);
        #pragma unroll
        for (int r = 0; r < N; ++r)
            o_s[r][c] = fmaf(t1g[r*D + c], sc1, sh1) + fmaf(t2g[r*D + c], sc2, sh2);
        __syncthreads();
        {
            float a0[N], a1[N];
            #pragma unroll
            for (int r = 0; r < N; ++r) { a0[r] = b1a; a1[r] = b1b; }
            #pragma unroll 2
            for (int k = 0; k < D; k += 4) {
                float wa0 = w1T[(k+0)*256 + c], wb0 = w1T[(k+0)*256 + 128 + c];
                float wa1 = w1T[(k+1)*256 + c], wb1 = w1T[(k+1)*256 + 128 + c];
                float wa2 = w1T[(k+2)*256 + c], wb2 = w1T[(k+2)*256 + 128 + c];
                float wa3 = w1T[(k+3)*256 + c], wb3 = w1T[(k+3)*256 + 128 + c];
                #pragma unroll
                for (int r = 0; r < N; ++r) {
                    float4 hv = *reinterpret_cast<const float4*>(&o_s[r][k]);
                    a0[r] = fmaf(hv.x, wa0, a0[r]);  a1[r] = fmaf(hv.x, wb0, a1[r]);
                    a0[r] = fmaf(hv.y, wa1, a0[r]);  a1[r] = fmaf(hv.y, wb1, a1[r]);
                    a0[r] = fmaf(hv.z, wa2, a0[r]);  a1[r] = fmaf(hv.z, wb2, a1[r]);
                    a0[r] = fmaf(hv.w, wa3, a0[r]);  a1[r] = fmaf(hv.w, wb3, a1[r]);
                }
            }
            #pragma unroll
            for (int r = 0; r < N; ++r) {
                u_s[r][c] = fmaxf(a0[r], 0.f); u_s[r][128 + c] = fmaxf(a1[r], 0.f);
            }
        }
        __syncthreads();
        {
            float a0[N];
            #pragma unroll
            for (int r = 0; r < N; ++r) a0[r] = b2a;
            #pragma unroll 2
            for (int j = 0; j < 256; j += 4) {
                float w0 = w2T[(j+0)*D + c], w1v = w2T[(j+1)*D + c];
                float w2v = w2T[(j+2)*D + c], w3 = w2T[(j+3)*D + c];
                #pragma unroll
                for (int r = 0; r < N; ++r) {
                    float4 uv = *reinterpret_cast<const float4*>(&u_s[r][j]);
                    a0[r] = fmaf(uv.x, w0, a0[r]); a0[r] = fmaf(uv.y, w1v, a0[r]);
                    a0[r] = fmaf(uv.z, w2v, a0[r]); a0[r] = fmaf(uv.w, w3, a0[r]);
                }
            }
            float* og = hout + (size_t)g * (N * D);
            #pragma unroll
            for (int r = 0; r < N; ++r) {
                float v = o_s[r][c] + a0[r];
                og[r*D + c] = v; s3 += v; q3 = fmaf(v, v, q3);
            }
        }
        __syncthreads();
    }
    atomicAdd(&acc[c], s3); atomicAdd(&acc[128 + c], q3);
}

extern "C" void kernel_launch(void* const* d_in, const int* in_sizes, int n_in,
                              void* d_out, int out_size) {
    const float* poses = (const float*)d_in[0];
    const float* emb_w = (const float*)d_in[1];
    const float* emb_b = (const float*)d_in[2];
    const float* cls_w = (const float*)d_in[3];
    const float* cls_b = (const float*)d_in[4];
    const float* PPj[12]; const float* PPi[12];
    for (int i = 0; i < 12; ++i) { PPj[i] = (const float*)d_in[5+i]; PPi[i] = (const float*)d_in[17+i]; }

    float *A, *Bb, *Cc, *A2, *B2, *C2, *acc, *fold, *wT; uint4* wf;
    cudaGetSymbolAddress((void**)&A,    g_A);
    cudaGetSymbolAddress((void**)&Bb,   g_B);
    cudaGetSymbolAddress((void**)&Cc,   g_C);
    cudaGetSymbolAddress((void**)&A2,   g_A2);
    cudaGetSymbolAddress((void**)&B2,   g_B2);
    cudaGetSymbolAddress((void**)&C2,   g_C2);
    cudaGetSymbolAddress((void**)&acc,  g_acc);
    cudaGetSymbolAddress((void**)&fold, g_fold);
    cudaGetSymbolAddress((void**)&wT,   g_wT);
    cudaGetSymbolAddress((void**)&wf,   g_wf4);
    const float* foldId = fold + 18 * 256;

    cudaFuncSetAttribute(k1_s1, cudaFuncAttributeMaxDynamicSharedMemorySize, SM1);
    cudaFuncSetAttribute(k2_s1, cudaFuncAttributeMaxDynamicSharedMemorySize, SM2);

    init_kernel<<<18, 256>>>(acc, fold + 18 * 256);

    // stage-1 weights: gw transposed (fp32), rest as paired mma fragments
    transpose_kernel<<<192, 256>>>(PPj[0], wT, 128, 128, 49152);
    for (int l = 0; l < 3; ++l) {
        prep_frag<<<24, 256>>>(PPj[2]  + l*49152, wf + l*16384,         48, 128, 6144);
        prep_frag<<< 8, 256>>>(PPj[4]  + l*16384, wf + l*16384 + 6144,  16, 128, 2048);
        prep_frag<<<16, 256>>>(PPj[8]  + l*32768, wf + l*16384 + 8192,  32, 128, 4096);
        prep_frag<<<16, 256>>>(PPj[10] + l*32768, wf + l*16384 + 12288, 16, 256, 4096);
    }
    // stage-2 weights: transposed fp32
    {
        float* wTs = wT + 442368;
        transpose_kernel<<<192, 256>>>(PPi[0],  wTs + 0,      128, 128, 49152);
        transpose_kernel<<<576, 256>>>(PPi[2],  wTs + 49152,  384, 128, 147456);
        transpose_kernel<<<192, 256>>>(PPi[4],  wTs + 196608, 128, 128, 49152);
        transpose_kernel<<<384, 256>>>(PPi[8],  wTs + 245760, 256, 128, 98304);
        transpose_kernel<<<384, 256>>>(PPi[10], wTs + 344064, 128, 256, 98304);
    }

    embed_kernel<<<182784, 256>>>(poses, emb_w, emb_b, A, 46792704);

    // stage 1 (tensor-core, 512 threads)
    const float* foldPrev = foldId;
    for (int l = 0; l < 3; ++l) {
        float* accL = acc + l * 768;
        float* foldL = fold + l * 768;
        k1_s1<<<5376, 512, SM1>>>(A, foldPrev, Bb, Cc, accL,
                                  wT + l*16384, PPj[1] + l*128, PPj[3] + l*384, PPj[5] + l*128,
                                  wf + l*16384, wf + l*16384 + 6144);
        finalize_kernel<<<2, 128>>>(accL, 1.f/365568.f, PPj[6] + l*384, PPj[7] + l*384, foldL,
                                    PPj[6] + l*384 + 128, PPj[7] + l*384 + 128, foldL + 256);
        k2_s1<<<2688, 512, SM2>>>(Bb, Cc, foldL, foldL + 256, A, accL + 512,
                                  wf + l*16384 + 8192, PPj[9] + l*256,
                                  wf + l*16384 + 12288, PPj[11] + l*128);
        finalize_kernel<<<1, 128>>>(accL + 512, 1.f/365568.f, PPj[6] + l*384 + 256,
                                    PPj[7] + l*384 + 256, foldL + 512, nullptr, nullptr, nullptr);
        foldPrev = foldL + 512;
    }

    pool1_kernel<<<10752, 256>>>(A, foldPrev, A2, 2752512);

    // stage 2 (scalar)
    foldPrev = foldId;
    float* wTs = wT + 442368;
    for (int l = 0; l < 3; ++l) {
        float* accL = acc + 2304 + l * 768;
        float* foldL = fold + 2304 + l * 768;
        k1_kernel<12, 2><<<896, 128>>>(A2, foldPrev, B2, C2, accL,
                                       wTs + l*16384, PPi[1] + l*128, wTs + 49152 + l*49152,
                                       PPi[3] + l*384, wTs + 196608 + l*16384, PPi[5] + l*128);
        finalize_kernel<<<2, 128>>>(accL, 1.f/21504.f, PPi[6] + l*384, PPi[7] + l*384, foldL,
                                    PPi[6] + l*384 + 128, PPi[7] + l*384 + 128, foldL + 256);
        k2_kernel<12, 2><<<896, 128>>>(B2, C2, foldL, foldL + 256, A2, accL + 512,
                                       wTs + 245760 + l*32768, PPi[9] + l*256,
                                       wTs + 344064 + l*32768, PPi[11] + l*128);
        finalize_kernel<<<1, 128>>>(accL + 512, 1.f/21504.f, PPi[6] + l*384 + 256,
                                    PPi[7] + l*384 + 256, foldL + 512, nullptr, nullptr, nullptr);
        foldPrev = foldL + 512;
    }

    pool2_cls_kernel<<<256, 128>>>(A2, foldPrev, cls_w, cls_b, (float*)d_out);
}

// round 8
// speedup vs baseline: 1.0133x; 1.0133x over previous
#include <cuda_runtime.h>
#include <cuda_fp16.h>
#include <stdint.h>

#define D 128
#define DPAD 132

static __device__ float g_A [46792704];
static __device__ float g_B [46792704];
static __device__ float g_C [46792704];
static __device__ float g_A2[ 2752512];
static __device__ float g_B2[ 2752512];
static __device__ float g_C2[ 2752512];
static __device__ float g_acc [18*256];
static __device__ float g_fold[19*256];
static __device__ float g_wT  [884736];
static __device__ uint2 g_wf  [98304];

__global__ void init_kernel(float* acc, float* foldId) {
    int t = blockIdx.x * blockDim.x + threadIdx.x;
    if (t < 18*256) acc[t] = 0.f;
    if (t < 128) { foldId[t] = 1.f; foldId[128 + t] = 0.f; }
}

__global__ void transpose_kernel(const float* __restrict__ src, float* __restrict__ dst,
                                 int R, int C, int total) {
    int idx = blockIdx.x * blockDim.x + threadIdx.x;
    if (idx >= total) return;
    int m = idx / (R * C), rc = idx - m * (R * C), cc = rc / R, r = rc - cc * R;
    dst[idx] = src[m * R * C + r * C + cc];
}

__global__ void prep_frag(const float* __restrict__ W, uint2* __restrict__ out,
                          int NT, int K, int total) {
    int idx = blockIdx.x * blockDim.x + threadIdx.x;
    if (idx >= total) return;
    int lane = idx & 31, tile = idx >> 5;
    int nt = tile % NT, kt = tile / NT;
    int g = lane >> 2, t = lane & 3;
    const float* w = W + (size_t)(nt * 8 + g) * K + kt * 16 + 2 * t;
    __half2 b0 = __floats2half2_rn(w[0], w[1]);
    __half2 b1 = __floats2half2_rn(w[8], w[9]);
    uint2 o; o.x = *(uint32_t*)&b0; o.y = *(uint32_t*)&b1;
    out[idx] = o;
}

__global__ void embed_kernel(const float* __restrict__ poses, const float* __restrict__ ew,
                             const float* __restrict__ eb, float* __restrict__ out, int total) {
    int idx = blockIdx.x * blockDim.x + threadIdx.x;
    if (idx >= total) return;
    int row = idx >> 7, c = idx & 127;
    float v = fmaf(poses[row*2], ew[2*c], fmaf(poses[row*2+1], ew[2*c+1], eb[c]));
    out[idx] = v > 0.f ? v : 0.01f * v;
}

__global__ void finalize_kernel(const float* __restrict__ acc, float invN,
                                const float* g0, const float* b0, float* f0,
                                const float* g1, const float* b1, float* f1) {
    int set = blockIdx.x, c = threadIdx.x;
    const float* a  = acc + set * 256;
    const float* gg = set ? g1 : g0;
    const float* bb = set ? b1 : b0;
    float* ff = set ? f1 : f0;
    float m = a[c] * invN;
    float v = fmaxf(a[128 + c] * invN - m * m, 0.f);
    float sc = rsqrtf(v + 1e-5f) * gg[c];
    ff[c] = sc;
    ff[128 + c] = fmaf(-m, sc, bb[c]);
}

__global__ void pool1_kernel(const float* __restrict__ hin, const float* __restrict__ fold,
                             float* __restrict__ out, int total) {
    int idx = blockIdx.x * blockDim.x + threadIdx.x;
    if (idx >= total) return;
    int orow = idx >> 7, c = idx & 127;
    const float* base = hin + (size_t)orow * 17 * D + c;
    float s = 0.f;
    #pragma unroll
    for (int j = 0; j < 17; ++j) s += base[j * D];
    out[idx] = fmaf(s * (1.f / 17.f), fold[c], fold[128 + c]);
}

__global__ void pool2_cls_kernel(const float* __restrict__ hin, const float* __restrict__ fold,
                                 const float* __restrict__ cw, const float* __restrict__ cb,
                                 float* __restrict__ out) {
    __shared__ float p_s[D];
    int b = blockIdx.x, c = threadIdx.x;
    const float* base = hin + (size_t)b * 84 * D + c;
    float s = 0.f;
    #pragma unroll 4
    for (int r = 0; r < 84; ++r) s += base[r * D];
    p_s[c] = fmaf(s * (1.f / 84.f), fold[c], fold[128 + c]);
    __syncthreads();
    if (c < 8) {
        float acc = cb[c];
        #pragma unroll 4
        for (int k = 0; k < D; ++k) acc = fmaf(p_s[k], cw[c * D + k], acc);
        out[b * 8 + c] = acc;
    }
}

__device__ __forceinline__ void mma16816(float* c, uint32_t a0, uint32_t a1,
                                         uint32_t a2, uint32_t a3, uint32_t b0, uint32_t b1) {
    asm("mma.sync.aligned.m16n8k16.row.col.f32.f16.f16.f32 "
        "{%0,%1,%2,%3},{%4,%5,%6,%7},{%8,%9},{%0,%1,%2,%3};"
        : "+f"(c[0]), "+f"(c[1]), "+f"(c[2]), "+f"(c[3])
        : "r"(a0), "r"(a1), "r"(a2), "r"(a3), "r"(b0), "r"(b1));
}

template<int KT, int NT>
__device__ __forceinline__ void mtile(const __half* a0p, int lda, const uint2* __restrict__ wf,
                                      int ng, int lane, float acc[4][4]) {
    const __half* a1p = a0p + 8 * lda;
    #pragma unroll
    for (int kt = 0; kt < KT; ++kt) {
        uint32_t a0 = *(const uint32_t*)(a0p + kt*16);
        uint32_t a1 = *(const uint32_t*)(a1p + kt*16);
        uint32_t a2 = *(const uint32_t*)(a0p + kt*16 + 8);
        uint32_t a3 = *(const uint32_t*)(a1p + kt*16 + 8);
        #pragma unroll
        for (int j = 0; j < 4; ++j) {
            uint2 b = wf[(kt*NT + ng*4 + j)*32 + lane];
            mma16816(acc[j], a0, a1, a2, a3, b.x, b.y);
        }
    }
}

// ---------------- stage-1 tensor kernels: 4 graphs (68 rows) per block -----
#define O_H16 0
#define O_Q16 21760
#define O_K16 43520
#define O_VT  65280
#define O_P   100096
#define O_SC  134912
#define O_MB  162112
#define O_H32 166208
#define SM1   202112

__global__ __launch_bounds__(256)
void k1_s1(const float* __restrict__ hin, const float* __restrict__ foldIn,
           float* __restrict__ gcnb, float* __restrict__ t2, float* __restrict__ accL,
           const float* __restrict__ gwT, const float* __restrict__ gb,
           const float* __restrict__ qb, const float* __restrict__ ob,
           const uint2* __restrict__ qkvf, const uint2* __restrict__ owf) {
    extern __shared__ char sm[];
    __half (*h16)[136] = (__half(*)[136])(sm + O_H16);
    __half (*q16)[136] = (__half(*)[136])(sm + O_Q16);
    __half (*k16)[136] = (__half(*)[136])(sm + O_K16);
    __half (*vT )[34]  = (__half(*)[34]) (sm + O_VT);
    __half (*pp )[34]  = (__half(*)[34]) (sm + O_P);
    float  (*sc )[25]  = (float(*)[25])  (sm + O_SC);
    float*  mbuf       = (float*)(sm + O_MB);
    float  (*h32)[132] = (float(*)[132]) (sm + O_H32);

    const int tid = threadIdx.x, warp = tid >> 5, lane = tid & 31;
    const int g = lane >> 2, t = lane & 3;
    const int colj = tid & 127;
    const float* hg = hin + (size_t)blockIdx.x * 8704;
    float* t2g = t2 + (size_t)blockIdx.x * 8704;
    const float scIn = foldIn[colj], shIn = foldIn[128 + colj];

    { // zero vT+pp + h16 pad rows; single read of hg -> h32 (fp32) + h16
        uint32_t* z = (uint32_t*)(sm + O_VT);
        for (int i = tid; i < 17408; i += 256) z[i] = 0;
        uint32_t* zh = (uint32_t*)&h16[68][0];
        for (int i = tid; i < 816; i += 256) zh[i] = 0;
        for (int i = tid; i < 8704; i += 256) {
            int rr = i >> 7;
            float v = fmaf(hg[i], scIn, shIn);
            h32[rr][colj] = v;
            h16[rr][colj] = __float2half_rn(v);
        }
    }
    __syncthreads();
    for (int j = tid; j < 512; j += 256) { // per-graph mean (fp32)
        int gi = j >> 7, cc = j & 127;
        float s = 0.f;
        #pragma unroll
        for (int r = 0; r < 17; ++r) s += h32[gi*17 + r][cc];
        mbuf[j] = s * (1.f / 17.f);
    }
    __syncthreads();
    for (int j = tid; j < 512; j += 256) { // GCN rank-1 -> smem + tiny global buffer
        int gi = j >> 7, cc = j & 127;
        float a = gb[cc];
        const float* mrow = mbuf + gi * 128;
        #pragma unroll 4
        for (int k = 0; k < 128; ++k) a = fmaf(mrow[k], gwT[k*128 + cc], a);
        mbuf[512 + j] = a;
        gcnb[(size_t)blockIdx.x * 512 + j] = a;
    }
    __syncthreads();
    { // t1 stats (column-aligned: i&127 == colj)
        float s1 = 0.f, q1 = 0.f;
        for (int i = tid; i < 8704; i += 256) {
            int rr = i >> 7;
            float v = mbuf[512 + (rr/17)*128 + colj] + h32[rr][colj];
            s1 += v; q1 = fmaf(v, v, q1);
        }
        float* red = (float*)sc;
        red[tid] = s1; red[256 + tid] = q1;
    }
    __syncthreads();
    if (tid < 128) {
        float* red = (float*)sc;
        atomicAdd(&accL[tid],       red[tid] + red[tid + 128]);
        atomicAdd(&accL[128 + tid], red[256 + tid] + red[384 + tid]);
    }
    // qkv: M=80, N=384, K=128
    for (int item = warp; item < 60; item += 8) {
        int mt = item / 12, ng = item % 12, m0 = mt * 16;
        float acc[4][4] = {};
        mtile<8,48>(&h16[m0 + g][2*t], 136, qkvf, ng, lane, acc);
        int r0 = m0 + g, r1 = r0 + 8;
        #pragma unroll
        for (int j = 0; j < 4; ++j) {
            int nc = ng*32 + j*8 + 2*t;
            float b0 = qb[nc], b1 = qb[nc+1];
            float v00 = acc[j][0]+b0, v01 = acc[j][1]+b1, v10 = acc[j][2]+b0, v11 = acc[j][3]+b1;
            if (nc < 128) {
                *(__half2*)&q16[r0][nc] = __floats2half2_rn(v00, v01);
                *(__half2*)&q16[r1][nc] = __floats2half2_rn(v10, v11);
            } else if (nc < 256) {
                *(__half2*)&k16[r0][nc-128] = __floats2half2_rn(v00, v01);
                *(__half2*)&k16[r1][nc-128] = __floats2half2_rn(v10, v11);
            } else {
                int d = nc - 256;
                if (r0 < 68) { int gi = r0/17, sl = r0 - gi*17;
                    vT[gi*128+d][sl] = __float2half_rn(v00); vT[gi*128+d+1][sl] = __float2half_rn(v01); }
                if (r1 < 68) { int gi = r1/17, sl = r1 - gi*17;
                    vT[gi*128+d][sl] = __float2half_rn(v10); vT[gi*128+d+1][sl] = __float2half_rn(v11); }
            }
        }
    }
    __syncthreads();
    // scores
    for (int item = warp; item < 96; item += 8) {
        int gi = item / 24, r = item % 24, hh = r / 6, r2 = r % 6, mt = r2 / 3, nt = r2 % 3;
        int base = gi * 17;
        float acc[4] = {};
        const __half* a0p = &q16[base + mt*16 + g][hh*32 + 2*t];
        const __half* a1p = a0p + 8*136;
        const __half* br  = &k16[base + nt*8 + g][hh*32 + 2*t];
        #pragma unroll
        for (int kt = 0; kt < 2; ++kt) {
            mma16816(acc, *(const uint32_t*)(a0p+kt*16), *(const uint32_t*)(a1p+kt*16),
                     *(const uint32_t*)(a0p+kt*16+8), *(const uint32_t*)(a1p+kt*16+8),
                     *(const uint32_t*)(br+kt*16), *(const uint32_t*)(br+kt*16+8));
        }
        const float invs = 0.17677669529663687f;
        int q0 = mt*16 + g, ss = nt*8 + 2*t, row = (gi*4 + hh)*17;
        if (q0 < 17)     { sc[row+q0][ss]   = acc[0]*invs; sc[row+q0][ss+1]   = acc[1]*invs; }
        if (q0 + 8 < 17) { sc[row+q0+8][ss] = acc[2]*invs; sc[row+q0+8][ss+1] = acc[3]*invs; }
    }
    __syncthreads();
    for (int idx = tid; idx < 272; idx += 256) { // softmax -> fp16 probs
        int gh = idx / 17, q = idx - gh*17;
        float e[17], mx = -1e30f;
        #pragma unroll
        for (int s = 0; s < 17; ++s) mx = fmaxf(mx, sc[gh*17+q][s]);
        float sum = 0.f;
        #pragma unroll
        for (int s = 0; s < 17; ++s) { e[s] = __expf(sc[gh*17+q][s] - mx); sum += e[s]; }
        float inv = 1.f / sum;
        #pragma unroll
        for (int s = 0; s < 17; ++s) pp[gh*32 + q][s] = __float2half_rn(e[s] * inv);
    }
    __syncthreads();
    // attn @ V -> q16 (reuse)
    for (int item = warp; item < 32; item += 8) {
        int gi = item / 8, r = item % 8, hh = r / 2, mt = r % 2;
        float acc[4][4] = {};
        const __half* a0p = &pp[(gi*4+hh)*32 + mt*16 + g][2*t];
        const __half* a1p = a0p + 8*34;
        #pragma unroll
        for (int kt = 0; kt < 2; ++kt) {
            uint32_t a0 = *(const uint32_t*)(a0p+kt*16), a1 = *(const uint32_t*)(a1p+kt*16);
            uint32_t a2 = *(const uint32_t*)(a0p+kt*16+8), a3 = *(const uint32_t*)(a1p+kt*16+8);
            #pragma unroll
            for (int j = 0; j < 4; ++j) {
                const __half* bp = &vT[gi*128 + hh*32 + j*8 + g][kt*16 + 2*t];
                mma16816(acc[j], a0, a1, a2, a3, *(const uint32_t*)bp, *(const uint32_t*)(bp+8));
            }
        }
        int q0 = mt*16 + g;
        #pragma unroll
        for (int j = 0; j < 4; ++j) {
            int col = hh*32 + j*8 + 2*t;
            if (q0 < 17)     *(__half2*)&q16[gi*17+q0][col]   = __floats2half2_rn(acc[j][0], acc[j][1]);
            if (q0 + 8 < 17) *(__half2*)&q16[gi*17+q0+8][col] = __floats2half2_rn(acc[j][2], acc[j][3]);
        }
    }
    __syncthreads();
    // out-proj + residual -> t2 (global) AND back into h32 (for channel-aligned stats)
    for (int item = warp; item < 20; item += 8) {
        int mt = item / 4, ng = item % 4, m0 = mt * 16;
        float acc[4][4] = {};
        mtile<8,16>(&q16[m0 + g][2*t], 136, owf, ng, lane, acc);
        int r0 = m0 + g, r1 = r0 + 8;
        #pragma unroll
        for (int j = 0; j < 4; ++j) {
            int nc = ng*32 + j*8 + 2*t;
            float b0 = ob[nc], b1 = ob[nc+1];
            if (r0 < 68) {
                float v0 = acc[j][0] + b0 + h32[r0][nc];
                float v1 = acc[j][1] + b1 + h32[r0][nc+1];
                t2g[r0*128+nc] = v0; t2g[r0*128+nc+1] = v1;
                h32[r0][nc] = v0; h32[r0][nc+1] = v1;
            }
            if (r1 < 68) {
                float v0 = acc[j][2] + b0 + h32[r1][nc];
                float v1 = acc[j][3] + b1 + h32[r1][nc+1];
                t2g[r1*128+nc] = v0; t2g[r1*128+nc+1] = v1;
                h32[r1][nc] = v0; h32[r1][nc+1] = v1;
            }
        }
    }
    __syncthreads();
    { // t2 stats, column-aligned from smem
        float s2 = 0.f, q2 = 0.f;
        for (int i = tid; i < 8704; i += 256) {
            float v = h32[i >> 7][colj];
            s2 += v; q2 = fmaf(v, v, q2);
        }
        mbuf[tid] = s2; mbuf[256 + tid] = q2;
        __syncthreads();
        if (tid < 128) {
            atomicAdd(&accL[256 + tid], mbuf[tid] + mbuf[tid + 128]);
            atomicAdd(&accL[384 + tid], mbuf[256 + tid] + mbuf[384 + tid]);
        }
    }
}

// 8 graphs (136 rows) per block
#define P_O16 0
#define P_U16 39168
#define P_O32 115200
#define P_GB  187008
#define SM2   191104

__global__ __launch_bounds__(256)
void k2_s1(const float* __restrict__ hg0, const float* __restrict__ gcnb,
           const float* __restrict__ t2, const float* __restrict__ foldIn,
           const float* __restrict__ fold1, const float* __restrict__ fold2,
           float* __restrict__ hout, float* __restrict__ accL,
           const uint2* __restrict__ w1f, const float* __restrict__ b1v,
           const uint2* __restrict__ w2f, const float* __restrict__ b2v) {
    extern __shared__ char sm[];
    __half (*o16)[136] = (__half(*)[136])(sm + P_O16);
    __half (*u16)[264] = (__half(*)[264])(sm + P_U16);
    float  (*o32)[132] = (float(*)[132]) (sm + P_O32);
    float*  gbuf       = (float*)(sm + P_GB);
    const int tid = threadIdx.x, warp = tid >> 5, lane = tid & 31;
    const int g = lane >> 2, t = lane & 3;
    const int colj = tid & 127;
    const float* hgA = hg0 + (size_t)blockIdx.x * 17408;
    const float* t2g = t2  + (size_t)blockIdx.x * 17408;
    float* og = hout + (size_t)blockIdx.x * 17408;
    const float scIn = foldIn[colj], shIn = foldIn[128 + colj];
    const float sc1 = fold1[colj], sh1 = fold1[128 + colj];
    const float sc2 = fold2[colj], sh2 = fold2[128 + colj];

    for (int j = tid; j < 1024; j += 256)
        gbuf[j] = gcnb[(size_t)blockIdx.x * 1024 + j];
    { // zero o16 pad rows 136-143
        uint32_t* zz = (uint32_t*)&o16[136][0];
        for (int i = tid; i < 544; i += 256) zz[i] = 0;
    }
    __syncthreads();
    // o = BN1(gcn + BN_in(h)) + BN2(t2)  -> o32 (fp32) + o16
    for (int i = tid; i < 17408; i += 256) {
        int rr = i >> 7;
        float t1v = gbuf[(rr/17)*128 + colj] + fmaf(hgA[i], scIn, shIn);
        float o = fmaf(t1v, sc1, sh1) + fmaf(t2g[i], sc2, sh2);
        o32[rr][colj] = o;
        o16[rr][colj] = __float2half_rn(o);
    }
    __syncthreads();
    // mlp1: M=144, N=256, K=128 (+ReLU)
    for (int item = warp; item < 72; item += 8) {
        int mt = item / 8, ng = item % 8, m0 = mt * 16;
        float acc[4][4] = {};
        mtile<8,32>(&o16[m0 + g][2*t], 136, w1f, ng, lane, acc);
        int r0 = m0 + g, r1 = r0 + 8;
        #pragma unroll
        for (int j = 0; j < 4; ++j) {
            int nc = ng*32 + j*8 + 2*t;
            float b0 = b1v[nc], b1 = b1v[nc+1];
            *(__half2*)&u16[r0][nc] = __floats2half2_rn(fmaxf(acc[j][0]+b0, 0.f), fmaxf(acc[j][1]+b1, 0.f));
            *(__half2*)&u16[r1][nc] = __floats2half2_rn(fmaxf(acc[j][2]+b0, 0.f), fmaxf(acc[j][3]+b1, 0.f));
        }
    }
    __syncthreads();
    // mlp2: M=144, N=128, K=256 + residual; result -> og (global) AND o32 (stats)
    for (int item = warp; item < 36; item += 8) {
        int mt = item / 4, ng = item % 4, m0 = mt * 16;
        float acc[4][4] = {};
        mtile<16,16>(&u16[m0 + g][2*t], 264, w2f, ng, lane, acc);
        int r0 = m0 + g, r1 = r0 + 8;
        #pragma unroll
        for (int j = 0; j < 4; ++j) {
            int nc = ng*32 + j*8 + 2*t;
            float b0 = b2v[nc], b1 = b2v[nc+1];
            if (r0 < 136) {
                float v0 = acc[j][0] + b0 + o32[r0][nc];
                float v1 = acc[j][1] + b1 + o32[r0][nc+1];
                og[r0*128+nc] = v0; og[r0*128+nc+1] = v1;
                o32[r0][nc] = v0; o32[r0][nc+1] = v1;
            }
            if (r1 < 136) {
                float v0 = acc[j][2] + b0 + o32[r1][nc];
                float v1 = acc[j][3] + b1 + o32[r1][nc+1];
                og[r1*128+nc] = v0; og[r1*128+nc+1] = v1;
                o32[r1][nc] = v0; o32[r1][nc+1] = v1;
            }
        }
    }
    __syncthreads();
    { // output stats, column-aligned from smem
        float s3 = 0.f, q3 = 0.f;
        for (int i = tid; i < 17408; i += 256) {
            float v = o32[i >> 7][colj];
            s3 += v; q3 = fmaf(v, v, q3);
        }
        float* red = (float*)u16;
        red[tid] = s3; red[256 + tid] = q3;
        __syncthreads();
        if (tid < 128) {
            atomicAdd(&accL[tid],       red[tid] + red[tid + 128]);
            atomicAdd(&accL[128 + tid], red[256 + tid] + red[384 + tid]);
        }
    }
}

// ---------------- stage-2 scalar path (proven) -----------------------------
template<int N>
__device__ __forceinline__ void gemm128(const float (*hs)[DPAD], const float* __restrict__ wT,
                                        int ldw, int cidx, float bias, float* out) {
    #pragma unroll
    for (int r = 0; r < N; ++r) out[r] = bias;
    #pragma unroll 2
    for (int k = 0; k < D; k += 4) {
        float w0 = wT[(k+0)*ldw + cidx], w1 = wT[(k+1)*ldw + cidx];
        float w2 = wT[(k+2)*ldw + cidx], w3 = wT[(k+3)*ldw + cidx];
        #pragma unroll
        for (int r = 0; r < N; ++r) {
            float4 hv = *reinterpret_cast<const float4*>(&hs[r][k]);
            out[r] = fmaf(hv.x, w0, out[r]); out[r] = fmaf(hv.y, w1, out[r]);
            out[r] = fmaf(hv.z, w2, out[r]); out[r] = fmaf(hv.w, w3, out[r]);
        }
    }
}

template<int N, int GPB>
__global__ __launch_bounds__(128)
void k1_kernel(const float* __restrict__ hin, const float* __restrict__ foldIn,
               float* __restrict__ t1, float* __restrict__ t2, float* __restrict__ acc,
               const float* __restrict__ gwT, const float* __restrict__ gb,
               const float* __restrict__ qwT, const float* __restrict__ qb,
               const float* __restrict__ owT, const float* __restrict__ ob) {
    __shared__ float h_s[N][DPAD], q_s[N][DPAD], k_s[N][DPAD], v_s[N][DPAD];
    __shared__ float sc_s[4][N][N + 1], m_s[D];
    const int c = threadIdx.x, wp = c >> 5, lane = c & 31;
    const float scIn = foldIn[c], shIn = foldIn[D + c];
    const float gbv = gb[c], obv = ob[c];
    const float qbq = qb[c], qbk = qb[D + c], qbv = qb[2*D + c];
    float s1 = 0.f, sq1 = 0.f, s2 = 0.f, sq2 = 0.f;
    for (int gi = 0; gi < GPB; ++gi) {
        const int g = blockIdx.x * GPB + gi;
        const float* hg = hin + (size_t)g * (N * D);
        float mv = 0.f;
        #pragma unroll
        for (int r = 0; r < N; ++r) {
            float v = fmaf(hg[r*D + c], scIn, shIn);
            h_s[r][c] = v; mv += v;
        }
        m_s[c] = mv * (1.f / N);
        __syncthreads();
        float gcnv = gbv;
        #pragma unroll 4
        for (int k = 0; k < D; ++k) gcnv = fmaf(m_s[k], gwT[k*D + c], gcnv);
        {
            float* t1g = t1 + (size_t)g * (N * D);
            #pragma unroll
            for (int r = 0; r < N; ++r) {
                float v = gcnv + h_s[r][c];
                t1g[r*D + c] = v; s1 += v; sq1 = fmaf(v, v, sq1);
            }
        }
        {
            float a[N];
            gemm128<N>(h_s, qwT, 384, c, qbq, a);
            #pragma unroll
            for (int r = 0; r < N; ++r) q_s[r][c] = a[r];
            gemm128<N>(h_s, qwT, 384, c + 128, qbk, a);
            #pragma unroll
            for (int r = 0; r < N; ++r) k_s[r][c] = a[r];
            gemm128<N>(h_s, qwT, 384, c + 256, qbv, a);
            #pragma unroll
            for (int r = 0; r < N; ++r) v_s[r][c] = a[r];
        }
        __syncthreads();
        {
            const float invs = 0.17677669529663687f;
            for (int p = lane; p < N * N; p += 32) {
                int r = p / N, s = p - r * N;
                float d0 = 0.f;
                #pragma unroll
                for (int d = 0; d < 32; d += 4) {
                    float4 qq = *reinterpret_cast<const float4*>(&q_s[r][wp*32 + d]);
                    float4 kk = *reinterpret_cast<const float4*>(&k_s[s][wp*32 + d]);
                    d0 = fmaf(qq.x, kk.x, d0); d0 = fmaf(qq.y, kk.y, d0);
                    d0 = fmaf(qq.z, kk.z, d0); d0 = fmaf(qq.w, kk.w, d0);
                }
                sc_s[wp][r][s] = d0 * invs;
            }
            __syncwarp();
            if (lane < N) {
                float mx = -1e30f;
                #pragma unroll
                for (int s = 0; s < N; ++s) mx = fmaxf(mx, sc_s[wp][lane][s]);
                float sum = 0.f;
                #pragma unroll
                for (int s = 0; s < N; ++s) { float e = __expf(sc_s[wp][lane][s] - mx); sc_s[wp][lane][s] = e; sum += e; }
                float inv = 1.f / sum;
                #pragma unroll
                for (int s = 0; s < N; ++s) sc_s[wp][lane][s] *= inv;
            }
            __syncwarp();
            #pragma unroll
            for (int r = 0; r < N; ++r) {
                float o = 0.f;
                #pragma unroll
                for (int s = 0; s < N; ++s) o = fmaf(sc_s[wp][r][s], v_s[s][wp*32 + lane], o);
                q_s[r][wp*32 + lane] = o;
            }
        }
        __syncthreads();
        {
            float a[N];
            gemm128<N>(q_s, owT, 128, c, obv, a);
            float* t2g = t2 + (size_t)g * (N * D);
            #pragma unroll
            for (int r = 0; r < N; ++r) {
                float v = a[r] + h_s[r][c];
                t2g[r*D + c] = v; s2 += v; sq2 = fmaf(v, v, sq2);
            }
        }
        __syncthreads();
    }
    atomicAdd(&acc[c], s1); atomicAdd(&acc[128 + c], sq1);
    atomicAdd(&acc[256 + c], s2); atomicAdd(&acc[384 + c], sq2);
}

template<int N, int GPB>
__global__ __launch_bounds__(128)
void k2_kernel(const float* __restrict__ t1, const float* __restrict__ t2,
               const float* __restrict__ fold1, const float* __restrict__ fold2,
               float* __restrict__ hout, float* __restrict__ acc,
               const float* __restrict__ w1T, const float* __restrict__ b1,
               const float* __restrict__ w2T, const float* __restrict__ b2) {
    __shared__ float o_s[N][DPAD], u_s[N][260];
    const int c = threadIdx.x;
    const float sc1 = fold1[c], sh1 = fold1[128 + c];
    const float sc2 = fold2[c], sh2 = fold2[128 + c];
    const float b1a = b1[c], b1b = b1[128 + c], b2a = b2[c];
    float s3 = 0.f, q3 = 0.f;
    for (int gi = 0; gi < GPB; ++gi) {
        const int g = blockIdx.x * GPB + gi;
        const float* t1g = t1 + (size_t)g * (N * D);
        const float* t2g = t2 + (size_t)g * (N * D);
        #pragma unroll
        for (int r = 0; r < N; ++r)
            o_s[r][c] = fmaf(t1g[r*D + c], sc1, sh1) + fmaf(t2g[r*D + c], sc2, sh2);
        __syncthreads();
        {
            float a0[N], a1[N];
            #pragma unroll
            for (int r = 0; r < N; ++r) { a0[r] = b1a; a1[r] = b1b; }
            #pragma unroll 2
            for (int k = 0; k < D; k += 4) {
                float wa0 = w1T[(k+0)*256 + c], wb0 = w1T[(k+0)*256 + 128 + c];
                float wa1 = w1T[(k+1)*256 + c], wb1 = w1T[(k+1)*256 + 128 + c];
                float wa2 = w1T[(k+2)*256 + c], wb2 = w1T[(k+2)*256 + 128 + c];
                float wa3 = w1T[(k+3)*256 + c], wb3 = w1T[(k+3)*256 + 128 + c];
                #pragma unroll
                for (int r = 0; r < N; ++r) {
                    float4 hv = *reinterpret_cast<const float4*>(&o_s[r][k]);
                    a0[r] = fmaf(hv.x, wa0, a0[r]);  a1[r] = fmaf(hv.x, wb0, a1[r]);
                    a0[r] = fmaf(hv.y, wa1, a0[r]);  a1[r] = fmaf(hv.y, wb1, a1[r]);
                    a0[r] = fmaf(hv.z, wa2, a0[r]);  a1[r] = fmaf(hv.z, wb2, a1[r]);
                    a0[r] = fmaf(hv.w, wa3, a0[r]);  a1[r] = fmaf(hv.w, wb3, a1[r]);
                }
            }
            #pragma unroll
            for (int r = 0; r < N; ++r) {
                u_s[r][c] = fmaxf(a0[r], 0.f); u_s[r][128 + c] = fmaxf(a1[r], 0.f);
            }
        }
        __syncthreads();
        {
            float a0[N];
            #pragma unroll
            for (int r = 0; r < N; ++r) a0[r] = b2a;
            #pragma unroll 2
            for (int j = 0; j < 256; j += 4) {
                float w0 = w2T[(j+0)*D + c], w1v = w2T[(j+1)*D + c];
                float w2v = w2T[(j+2)*D + c], w3 = w2T[(j+3)*D + c];
                #pragma unroll
                for (int r = 0; r < N; ++r) {
                    float4 uv = *reinterpret_cast<const float4*>(&u_s[r][j]);
                    a0[r] = fmaf(uv.x, w0, a0[r]); a0[r] = fmaf(uv.y, w1v, a0[r]);
                    a0[r] = fmaf(uv.z, w2v, a0[r]); a0[r] = fmaf(uv.w, w3, a0[r]);
                }
            }
            float* og = hout + (size_t)g * (N * D);
            #pragma unroll
            for (int r = 0; r < N; ++r) {
                float v = o_s[r][c] + a0[r];
                og[r*D + c] = v; s3 += v; q3 = fmaf(v, v, q3);
            }
        }
        __syncthreads();
    }
    atomicAdd(&acc[c], s3); atomicAdd(&acc[128 + c], q3);
}

extern "C" void kernel_launch(void* const* d_in, const int* in_sizes, int n_in,
                              void* d_out, int out_size) {
    const float* poses = (const float*)d_in[0];
    const float* emb_w = (const float*)d_in[1];
    const float* emb_b = (const float*)d_in[2];
    const float* cls_w = (const float*)d_in[3];
    const float* cls_b = (const float*)d_in[4];
    const float* PPj[12]; const float* PPi[12];
    for (int i = 0; i < 12; ++i) { PPj[i] = (const float*)d_in[5+i]; PPi[i] = (const float*)d_in[17+i]; }

    float *A, *Bb, *Cc, *A2, *B2, *C2, *acc, *fold, *wT; uint2* wf;
    cudaGetSymbolAddress((void**)&A,    g_A);
    cudaGetSymbolAddress((void**)&Bb,   g_B);
    cudaGetSymbolAddress((void**)&Cc,   g_C);
    cudaGetSymbolAddress((void**)&A2,   g_A2);
    cudaGetSymbolAddress((void**)&B2,   g_B2);
    cudaGetSymbolAddress((void**)&C2,   g_C2);
    cudaGetSymbolAddress((void**)&acc,  g_acc);
    cudaGetSymbolAddress((void**)&fold, g_fold);
    cudaGetSymbolAddress((void**)&wT,   g_wT);
    cudaGetSymbolAddress((void**)&wf,   g_wf);
    const float* foldId = fold + 18 * 256;

    cudaFuncSetAttribute(k1_s1, cudaFuncAttributeMaxDynamicSharedMemorySize, SM1);
    cudaFuncSetAttribute(k2_s1, cudaFuncAttributeMaxDynamicSharedMemorySize, SM2);

    init_kernel<<<18, 256>>>(acc, fold + 18 * 256);

    transpose_kernel<<<192, 256>>>(PPj[0], wT, 128, 128, 49152);
    for (int l = 0; l < 3; ++l) {
        prep_frag<<<48, 256>>>(PPj[2]  + l*49152, wf + l*32768,          48, 128, 12288);
        prep_frag<<<16, 256>>>(PPj[4]  + l*16384, wf + l*32768 + 12288,  16, 128, 4096);
        prep_frag<<<32, 256>>>(PPj[8]  + l*32768, wf + l*32768 + 16384,  32, 128, 8192);
        prep_frag<<<32, 256>>>(PPj[10] + l*32768, wf + l*32768 + 24576,  16, 256, 8192);
    }
    {
        float* wTs = wT + 442368;
        transpose_kernel<<<192, 256>>>(PPi[0],  wTs + 0,      128, 128, 49152);
        transpose_kernel<<<576, 256>>>(PPi[2],  wTs + 49152,  384, 128, 147456);
        transpose_kernel<<<192, 256>>>(PPi[4],  wTs + 196608, 128, 128, 49152);
        transpose_kernel<<<384, 256>>>(PPi[8],  wTs + 245760, 256, 128, 98304);
        transpose_kernel<<<384, 256>>>(PPi[10], wTs + 344064, 128, 256, 98304);
    }

    embed_kernel<<<182784, 256>>>(poses, emb_w, emb_b, A, 46792704);

    // stage 1 (tensor-core, traffic-minimized: t1 replaced by rank-1 gcn buffer in Bb)
    const float* foldPrev = foldId;
    for (int l = 0; l < 3; ++l) {
        float* accL = acc + l * 768;
        float* foldL = fold + l * 768;
        k1_s1<<<5376, 256, SM1>>>(A, foldPrev, Bb, Cc, accL,
                                  wT + l*16384, PPj[1] + l*128, PPj[3] + l*384, PPj[5] + l*128,
                                  wf + l*32768, wf + l*32768 + 12288);
        finalize_kernel<<<2, 128>>>(accL, 1.f/365568.f, PPj[6] + l*384, PPj[7] + l*384, foldL,
                                    PPj[6] + l*384 + 128, PPj[7] + l*384 + 128, foldL + 256);
        k2_s1<<<2688, 256, SM2>>>(A, Bb, Cc, foldPrev, foldL, foldL + 256, A, accL + 512,
                                  wf + l*32768 + 16384, PPj[9] + l*256,
                                  wf + l*32768 + 24576, PPj[11] + l*128);
        finalize_kernel<<<1, 128>>>(accL + 512, 1.f/365568.f, PPj[6] + l*384 + 256,
                                    PPj[7] + l*384 + 256, foldL + 512, nullptr, nullptr, nullptr);
        foldPrev = foldL + 512;
    }

    pool1_kernel<<<10752, 256>>>(A, foldPrev, A2, 2752512);

    // stage 2 (scalar)
    foldPrev = foldId;
    float* wTs = wT + 442368;
    for (int l = 0; l < 3; ++l) {
        float* accL = acc + 2304 + l * 768;
        float* foldL = fold + 2304 + l * 768;
        k1_kernel<12, 2><<<896, 128>>>(A2, foldPrev, B2, C2, accL,
                                       wTs + l*16384, PPi[1] + l*128, wTs + 49152 + l*49152,
                                       PPi[3] + l*384, wTs + 196608 + l*16384, PPi[5] + l*128);
        finalize_kernel<<<2, 128>>>(accL, 1.f/21504.f, PPi[6] + l*384, PPi[7] + l*384, foldL,
                                    PPi[6] + l*384 + 128, PPi[7] + l*384 + 128, foldL + 256);
        k2_kernel<12, 2><<<896, 128>>>(B2, C2, foldL, foldL + 256, A2, accL + 512,
                                       wTs + 245760 + l*32768, PPi[9] + l*256,
                                       wTs + 344064 + l*32768, PPi[11] + l*128);
        finalize_kernel<<<1, 128>>>(accL + 512, 1.f/21504.f, PPi[6] + l*384 + 256,
                                    PPi[7] + l*384 + 256, foldL + 512, nullptr, nullptr, nullptr);
        foldPrev = foldL + 512;
    }

    pool2_cls_kernel<<<256, 128>>>(A2, foldPrev, cls_w, cls_b, (float*)d_out);
}

// round 9
// speedup vs baseline: 1.2005x; 1.1847x over previous
#include <cuda_runtime.h>
#include <cuda_fp16.h>
#include <stdint.h>

#define D 128
#define DPAD 132

static __device__ float g_A [46792704];
static __device__ float g_B [46792704];
static __device__ float g_C [46792704];
static __device__ float g_A2[ 2752512];
static __device__ float g_B2[ 2752512];
static __device__ float g_C2[ 2752512];
static __device__ float g_acc [18*256];
static __device__ float g_fold[19*256];
static __device__ float g_wT  [884736];
static __device__ uint2 g_wf  [98304];

__global__ void init_kernel(float* acc, float* foldId) {
    int t = blockIdx.x * blockDim.x + threadIdx.x;
    if (t < 18*256) acc[t] = 0.f;
    if (t < 128) { foldId[t] = 1.f; foldId[128 + t] = 0.f; }
}

__global__ void transpose_kernel(const float* __restrict__ src, float* __restrict__ dst,
                                 int R, int C, int total) {
    int idx = blockIdx.x * blockDim.x + threadIdx.x;
    if (idx >= total) return;
    int m = idx / (R * C), rc = idx - m * (R * C), cc = rc / R, r = rc - cc * R;
    dst[idx] = src[m * R * C + r * C + cc];
}

__global__ void prep_frag(const float* __restrict__ W, uint2* __restrict__ out,
                          int NT, int K, int total) {
    int idx = blockIdx.x * blockDim.x + threadIdx.x;
    if (idx >= total) return;
    int lane = idx & 31, tile = idx >> 5;
    int nt = tile % NT, kt = tile / NT;
    int g = lane >> 2, t = lane & 3;
    const float* w = W + (size_t)(nt * 8 + g) * K + kt * 16 + 2 * t;
    __half2 b0 = __floats2half2_rn(w[0], w[1]);
    __half2 b1 = __floats2half2_rn(w[8], w[9]);
    uint2 o; o.x = *(uint32_t*)&b0; o.y = *(uint32_t*)&b1;
    out[idx] = o;
}

__global__ void embed_kernel(const float* __restrict__ poses, const float* __restrict__ ew,
                             const float* __restrict__ eb, float* __restrict__ out, int total) {
    int idx = blockIdx.x * blockDim.x + threadIdx.x;
    if (idx >= total) return;
    int row = idx >> 7, c = idx & 127;
    float v = fmaf(poses[row*2], ew[2*c], fmaf(poses[row*2+1], ew[2*c+1], eb[c]));
    out[idx] = v > 0.f ? v : 0.01f * v;
}

__global__ void finalize_kernel(const float* __restrict__ acc, float invN,
                                const float* g0, const float* b0, float* f0,
                                const float* g1, const float* b1, float* f1) {
    int set = blockIdx.x, c = threadIdx.x;
    const float* a  = acc + set * 256;
    const float* gg = set ? g1 : g0;
    const float* bb = set ? b1 : b0;
    float* ff = set ? f1 : f0;
    float m = a[c] * invN;
    float v = fmaxf(a[128 + c] * invN - m * m, 0.f);
    float sc = rsqrtf(v + 1e-5f) * gg[c];
    ff[c] = sc;
    ff[128 + c] = fmaf(-m, sc, bb[c]);
}

__global__ void pool1_kernel(const float* __restrict__ hin, const float* __restrict__ fold,
                             float* __restrict__ out, int total) {
    int idx = blockIdx.x * blockDim.x + threadIdx.x;
    if (idx >= total) return;
    int orow = idx >> 7, c = idx & 127;
    const float* base = hin + (size_t)orow * 17 * D + c;
    float s = 0.f;
    #pragma unroll
    for (int j = 0; j < 17; ++j) s += base[j * D];
    out[idx] = fmaf(s * (1.f / 17.f), fold[c], fold[128 + c]);
}

__global__ void pool2_cls_kernel(const float* __restrict__ hin, const float* __restrict__ fold,
                                 const float* __restrict__ cw, const float* __restrict__ cb,
                                 float* __restrict__ out) {
    __shared__ float p_s[D];
    int b = blockIdx.x, c = threadIdx.x;
    const float* base = hin + (size_t)b * 84 * D + c;
    float s = 0.f;
    #pragma unroll 4
    for (int r = 0; r < 84; ++r) s += base[r * D];
    p_s[c] = fmaf(s * (1.f / 84.f), fold[c], fold[128 + c]);
    __syncthreads();
    if (c < 8) {
        float acc = cb[c];
        #pragma unroll 4
        for (int k = 0; k < D; ++k) acc = fmaf(p_s[k], cw[c * D + k], acc);
        out[b * 8 + c] = acc;
    }
}

__device__ __forceinline__ void mma16816(float* c, uint32_t a0, uint32_t a1,
                                         uint32_t a2, uint32_t a3, uint32_t b0, uint32_t b1) {
    asm("mma.sync.aligned.m16n8k16.row.col.f32.f16.f16.f32 "
        "{%0,%1,%2,%3},{%4,%5,%6,%7},{%8,%9},{%0,%1,%2,%3};"
        : "+f"(c[0]), "+f"(c[1]), "+f"(c[2]), "+f"(c[3])
        : "r"(a0), "r"(a1), "r"(a2), "r"(a3), "r"(b0), "r"(b1));
}

template<int KT, int NT>
__device__ __forceinline__ void mtile(const __half* a0p, int lda, const uint2* __restrict__ wf,
                                      int ng, int lane, float acc[4][4]) {
    const __half* a1p = a0p + 8 * lda;
    #pragma unroll
    for (int kt = 0; kt < KT; ++kt) {
        uint32_t a0 = *(const uint32_t*)(a0p + kt*16);
        uint32_t a1 = *(const uint32_t*)(a1p + kt*16);
        uint32_t a2 = *(const uint32_t*)(a0p + kt*16 + 8);
        uint32_t a3 = *(const uint32_t*)(a1p + kt*16 + 8);
        #pragma unroll
        for (int j = 0; j < 4; ++j) {
            uint2 b = wf[(kt*NT + ng*4 + j)*32 + lane];
            mma16816(acc[j], a0, a1, a2, a3, b.x, b.y);
        }
    }
}

// ---------------- stage-1 tensor kernels: 2 graphs (34 rows), 2 CTAs/SM ----
#define O_H16 0
#define O_Q16 13056
#define O_K16 26112
#define O_VT  39168
#define O_P   56576
#define O_SC  73984
#define O_MB  87584
#define O_H32 91680
#define SM1   109632

__global__ __launch_bounds__(256, 2)
void k1_s1(const float* __restrict__ hin, const float* __restrict__ foldIn,
           float* __restrict__ gcnb, float* __restrict__ t2, float* __restrict__ accL,
           const float* __restrict__ gwT, const float* __restrict__ gb,
           const float* __restrict__ qb, const float* __restrict__ ob,
           const uint2* __restrict__ qkvf, const uint2* __restrict__ owf) {
    extern __shared__ char sm[];
    __half (*h16)[136] = (__half(*)[136])(sm + O_H16);   // [48][136]
    __half (*q16)[136] = (__half(*)[136])(sm + O_Q16);   // [48][136]
    __half (*k16)[136] = (__half(*)[136])(sm + O_K16);   // [48][136]
    __half (*vT )[34]  = (__half(*)[34]) (sm + O_VT);    // [2*128][34]
    __half (*pp )[34]  = (__half(*)[34]) (sm + O_P);     // [2*4*32][34]
    float  (*sc )[25]  = (float(*)[25])  (sm + O_SC);    // [136][25]
    float*  mbuf       = (float*)(sm + O_MB);            // 1024 floats
    float  (*h32)[132] = (float(*)[132]) (sm + O_H32);   // [34][132]

    const int tid = threadIdx.x, warp = tid >> 5, lane = tid & 31;
    const int g = lane >> 2, t = lane & 3;
    const int colj = tid & 127;
    const float* hg = hin + (size_t)blockIdx.x * 4352;
    float* t2g = t2 + (size_t)blockIdx.x * 4352;
    const float scIn = foldIn[colj], shIn = foldIn[128 + colj];

    { // zero vT+pp (contiguous 34816B) + h16 pad rows; single read -> h32+h16
        uint32_t* z = (uint32_t*)(sm + O_VT);
        for (int i = tid; i < 8704; i += 256) z[i] = 0;
        uint32_t* zh = (uint32_t*)&h16[34][0];
        for (int i = tid; i < 952; i += 256) zh[i] = 0;
        for (int i = tid; i < 4352; i += 256) {
            int rr = i >> 7;
            float v = fmaf(hg[i], scIn, shIn);
            h32[rr][colj] = v;
            h16[rr][colj] = __float2half_rn(v);
        }
    }
    __syncthreads();
    if (tid < 256) { // per-graph mean (256 channels: 2 graphs x 128)
        int gi = tid >> 7, cc = tid & 127;
        float s = 0.f;
        #pragma unroll
        for (int r = 0; r < 17; ++r) s += h32[gi*17 + r][cc];
        mbuf[tid] = s * (1.f / 17.f);
    }
    __syncthreads();
    { // GCN rank-1 -> smem + tiny global buffer
        int gi = tid >> 7, cc = tid & 127;
        float a = gb[cc];
        const float* mrow = mbuf + gi * 128;
        #pragma unroll 4
        for (int k = 0; k < 128; ++k) a = fmaf(mrow[k], gwT[k*128 + cc], a);
        mbuf[256 + tid] = a;
        gcnb[(size_t)blockIdx.x * 256 + tid] = a;
    }
    __syncthreads();
    { // t1 stats (t1 never materialized; column-aligned)
        float s1 = 0.f, q1 = 0.f;
        for (int i = tid; i < 4352; i += 256) {
            int rr = i >> 7;
            float v = mbuf[256 + (rr/17)*128 + colj] + h32[rr][colj];
            s1 += v; q1 = fmaf(v, v, q1);
        }
        float* red = (float*)sc;
        red[tid] = s1; red[256 + tid] = q1;
    }
    __syncthreads();
    if (tid < 128) {
        float* red = (float*)sc;
        atomicAdd(&accL[tid],       red[tid] + red[tid + 128]);
        atomicAdd(&accL[128 + tid], red[256 + tid] + red[384 + tid]);
    }
    // qkv: M=48, N=384, K=128
    for (int item = warp; item < 36; item += 8) {
        int mt = item / 12, ng = item % 12, m0 = mt * 16;
        float acc[4][4] = {};
        mtile<8,48>(&h16[m0 + g][2*t], 136, qkvf, ng, lane, acc);
        int r0 = m0 + g, r1 = r0 + 8;
        #pragma unroll
        for (int j = 0; j < 4; ++j) {
            int nc = ng*32 + j*8 + 2*t;
            float b0 = qb[nc], b1 = qb[nc+1];
            float v00 = acc[j][0]+b0, v01 = acc[j][1]+b1, v10 = acc[j][2]+b0, v11 = acc[j][3]+b1;
            if (nc < 128) {
                *(__half2*)&q16[r0][nc] = __floats2half2_rn(v00, v01);
                *(__half2*)&q16[r1][nc] = __floats2half2_rn(v10, v11);
            } else if (nc < 256) {
                *(__half2*)&k16[r0][nc-128] = __floats2half2_rn(v00, v01);
                *(__half2*)&k16[r1][nc-128] = __floats2half2_rn(v10, v11);
            } else {
                int d = nc - 256;
                if (r0 < 34) { int gi = r0/17, sl = r0 - gi*17;
                    vT[gi*128+d][sl] = __float2half_rn(v00); vT[gi*128+d+1][sl] = __float2half_rn(v01); }
                if (r1 < 34) { int gi = r1/17, sl = r1 - gi*17;
                    vT[gi*128+d][sl] = __float2half_rn(v10); vT[gi*128+d+1][sl] = __float2half_rn(v11); }
            }
        }
    }
    __syncthreads();
    // scores: 2 graphs x 4 heads x (2 mt x 3 nt)
    for (int item = warp; item < 48; item += 8) {
        int gi = item / 24, r = item % 24, hh = r / 6, r2 = r % 6, mt = r2 / 3, nt = r2 % 3;
        int base = gi * 17;
        float acc[4] = {};
        const __half* a0p = &q16[base + mt*16 + g][hh*32 + 2*t];
        const __half* a1p = a0p + 8*136;
        const __half* br  = &k16[base + nt*8 + g][hh*32 + 2*t];
        #pragma unroll
        for (int kt = 0; kt < 2; ++kt) {
            mma16816(acc, *(const uint32_t*)(a0p+kt*16), *(const uint32_t*)(a1p+kt*16),
                     *(const uint32_t*)(a0p+kt*16+8), *(const uint32_t*)(a1p+kt*16+8),
                     *(const uint32_t*)(br+kt*16), *(const uint32_t*)(br+kt*16+8));
        }
        const float invs = 0.17677669529663687f;
        int q0 = mt*16 + g, ss = nt*8 + 2*t, row = (gi*4 + hh)*17;
        if (q0 < 17)     { sc[row+q0][ss]   = acc[0]*invs; sc[row+q0][ss+1]   = acc[1]*invs; }
        if (q0 + 8 < 17) { sc[row+q0+8][ss] = acc[2]*invs; sc[row+q0+8][ss+1] = acc[3]*invs; }
    }
    __syncthreads();
    for (int idx = tid; idx < 136; idx += 256) { // softmax -> fp16 probs
        int gh = idx / 17, q = idx - gh*17;
        float e[17], mx = -1e30f;
        #pragma unroll
        for (int s = 0; s < 17; ++s) mx = fmaxf(mx, sc[gh*17+q][s]);
        float sum = 0.f;
        #pragma unroll
        for (int s = 0; s < 17; ++s) { e[s] = __expf(sc[gh*17+q][s] - mx); sum += e[s]; }
        float inv = 1.f / sum;
        #pragma unroll
        for (int s = 0; s < 17; ++s) pp[gh*32 + q][s] = __float2half_rn(e[s] * inv);
    }
    __syncthreads();
    // attn @ V -> q16 (reuse): 2 x 4 x 2 = 16 items
    for (int item = warp; item < 16; item += 8) {
        int gi = item / 8, r = item % 8, hh = r / 2, mt = r % 2;
        float acc[4][4] = {};
        const __half* a0p = &pp[(gi*4+hh)*32 + mt*16 + g][2*t];
        const __half* a1p = a0p + 8*34;
        #pragma unroll
        for (int kt = 0; kt < 2; ++kt) {
            uint32_t a0 = *(const uint32_t*)(a0p+kt*16), a1 = *(const uint32_t*)(a1p+kt*16);
            uint32_t a2 = *(const uint32_t*)(a0p+kt*16+8), a3 = *(const uint32_t*)(a1p+kt*16+8);
            #pragma unroll
            for (int j = 0; j < 4; ++j) {
                const __half* bp = &vT[gi*128 + hh*32 + j*8 + g][kt*16 + 2*t];
                mma16816(acc[j], a0, a1, a2, a3, *(const uint32_t*)bp, *(const uint32_t*)(bp+8));
            }
        }
        int q0 = mt*16 + g;
        #pragma unroll
        for (int j = 0; j < 4; ++j) {
            int col = hh*32 + j*8 + 2*t;
            if (q0 < 17)     *(__half2*)&q16[gi*17+q0][col]   = __floats2half2_rn(acc[j][0], acc[j][1]);
            if (q0 + 8 < 17) *(__half2*)&q16[gi*17+q0+8][col] = __floats2half2_rn(acc[j][2], acc[j][3]);
        }
    }
    __syncthreads();
    // out-proj + residual -> t2 (global) AND back into h32 (stats)
    for (int item = warp; item < 12; item += 8) {
        int mt = item / 4, ng = item % 4, m0 = mt * 16;
        float acc[4][4] = {};
        mtile<8,16>(&q16[m0 + g][2*t], 136, owf, ng, lane, acc);
        int r0 = m0 + g, r1 = r0 + 8;
        #pragma unroll
        for (int j = 0; j < 4; ++j) {
            int nc = ng*32 + j*8 + 2*t;
            float b0 = ob[nc], b1 = ob[nc+1];
            if (r0 < 34) {
                float v0 = acc[j][0] + b0 + h32[r0][nc];
                float v1 = acc[j][1] + b1 + h32[r0][nc+1];
                t2g[r0*128+nc] = v0; t2g[r0*128+nc+1] = v1;
                h32[r0][nc] = v0; h32[r0][nc+1] = v1;
            }
            if (r1 < 34) {
                float v0 = acc[j][2] + b0 + h32[r1][nc];
                float v1 = acc[j][3] + b1 + h32[r1][nc+1];
                t2g[r1*128+nc] = v0; t2g[r1*128+nc+1] = v1;
                h32[r1][nc] = v0; h32[r1][nc+1] = v1;
            }
        }
    }
    __syncthreads();
    { // t2 stats, column-aligned from smem
        float s2 = 0.f, q2 = 0.f;
        for (int i = tid; i < 4352; i += 256) {
            float v = h32[i >> 7][colj];
            s2 += v; q2 = fmaf(v, v, q2);
        }
        mbuf[tid] = s2; mbuf[256 + tid] = q2;
        __syncthreads();
        if (tid < 128) {
            atomicAdd(&accL[256 + tid], mbuf[tid] + mbuf[tid + 128]);
            atomicAdd(&accL[384 + tid], mbuf[256 + tid] + mbuf[384 + tid]);
        }
    }
}

// 4 graphs (68 rows) per block, 2 CTAs/SM
#define P_O16 0
#define P_U16 21760
#define P_O32 64000
#define P_GB  99904
#define SM2   101952

__global__ __launch_bounds__(256, 2)
void k2_s1(const float* __restrict__ hg0, const float* __restrict__ gcnb,
           const float* __restrict__ t2, const float* __restrict__ foldIn,
           const float* __restrict__ fold1, const float* __restrict__ fold2,
           float* __restrict__ hout, float* __restrict__ accL,
           const uint2* __restrict__ w1f, const float* __restrict__ b1v,
           const uint2* __restrict__ w2f, const float* __restrict__ b2v) {
    extern __shared__ char sm[];
    __half (*o16)[136] = (__half(*)[136])(sm + P_O16);   // [80][136]
    __half (*u16)[264] = (__half(*)[264])(sm + P_U16);   // [80][264]
    float  (*o32)[132] = (float(*)[132]) (sm + P_O32);   // [68][132]
    float*  gbuf       = (float*)(sm + P_GB);            // 512 floats
    const int tid = threadIdx.x, warp = tid >> 5, lane = tid & 31;
    const int g = lane >> 2, t = lane & 3;
    const int colj = tid & 127;
    const float* hgA = hg0 + (size_t)blockIdx.x * 8704;
    const float* t2g = t2  + (size_t)blockIdx.x * 8704;
    float* og = hout + (size_t)blockIdx.x * 8704;
    const float scIn = foldIn[colj], shIn = foldIn[128 + colj];
    const float sc1 = fold1[colj], sh1 = fold1[128 + colj];
    const float sc2 = fold2[colj], sh2 = fold2[128 + colj];

    for (int j = tid; j < 512; j += 256)
        gbuf[j] = gcnb[(size_t)blockIdx.x * 512 + j];
    { // zero o16 pad rows 68-79
        uint32_t* zz = (uint32_t*)&o16[68][0];
        for (int i = tid; i < 816; i += 256) zz[i] = 0;
    }
    __syncthreads();
    // o = BN1(gcn + BN_in(h)) + BN2(t2)  -> o32 (fp32) + o16
    for (int i = tid; i < 8704; i += 256) {
        int rr = i >> 7;
        float t1v = gbuf[(rr/17)*128 + colj] + fmaf(hgA[i], scIn, shIn);
        float o = fmaf(t1v, sc1, sh1) + fmaf(t2g[i], sc2, sh2);
        o32[rr][colj] = o;
        o16[rr][colj] = __float2half_rn(o);
    }
    __syncthreads();
    // mlp1: M=80, N=256, K=128 (+ReLU): 5 x 8 = 40 items
    for (int item = warp; item < 40; item += 8) {
        int mt = item / 8, ng = item % 8, m0 = mt * 16;
        float acc[4][4] = {};
        mtile<8,32>(&o16[m0 + g][2*t], 136, w1f, ng, lane, acc);
        int r0 = m0 + g, r1 = r0 + 8;
        #pragma unroll
        for (int j = 0; j < 4; ++j) {
            int nc = ng*32 + j*8 + 2*t;
            float b0 = b1v[nc], b1 = b1v[nc+1];
            *(__half2*)&u16[r0][nc] = __floats2half2_rn(fmaxf(acc[j][0]+b0, 0.f), fmaxf(acc[j][1]+b1, 0.f));
            *(__half2*)&u16[r1][nc] = __floats2half2_rn(fmaxf(acc[j][2]+b0, 0.f), fmaxf(acc[j][3]+b1, 0.f));
        }
    }
    __syncthreads();
    // mlp2: M=80, N=128, K=256 + residual -> og AND o32 (stats): 5 x 4 = 20 items
    for (int item = warp; item < 20; item += 8) {
        int mt = item / 4, ng = item % 4, m0 = mt * 16;
        float acc[4][4] = {};
        mtile<16,16>(&u16[m0 + g][2*t], 264, w2f, ng, lane, acc);
        int r0 = m0 + g, r1 = r0 + 8;
        #pragma unroll
        for (int j = 0; j < 4; ++j) {
            int nc = ng*32 + j*8 + 2*t;
            float b0 = b2v[nc], b1 = b2v[nc+1];
            if (r0 < 68) {
                float v0 = acc[j][0] + b0 + o32[r0][nc];
                float v1 = acc[j][1] + b1 + o32[r0][nc+1];
                og[r0*128+nc] = v0; og[r0*128+nc+1] = v1;
                o32[r0][nc] = v0; o32[r0][nc+1] = v1;
            }
            if (r1 < 68) {
                float v0 = acc[j][2] + b0 + o32[r1][nc];
                float v1 = acc[j][3] + b1 + o32[r1][nc+1];
                og[r1*128+nc] = v0; og[r1*128+nc+1] = v1;
                o32[r1][nc] = v0; o32[r1][nc+1] = v1;
            }
        }
    }
    __syncthreads();
    { // output stats, column-aligned from smem
        float s3 = 0.f, q3 = 0.f;
        for (int i = tid; i < 8704; i += 256) {
            float v = o32[i >> 7][colj];
            s3 += v; q3 = fmaf(v, v, q3);
        }
        float* red = (float*)u16;
        red[tid] = s3; red[256 + tid] = q3;
        __syncthreads();
        if (tid < 128) {
            atomicAdd(&accL[tid],       red[tid] + red[tid + 128]);
            atomicAdd(&accL[128 + tid], red[256 + tid] + red[384 + tid]);
        }
    }
}

// ---------------- stage-2 scalar path (proven) -----------------------------
template<int N>
__device__ __forceinline__ void gemm128(const float (*hs)[DPAD], const float* __restrict__ wT,
                                        int ldw, int cidx, float bias, float* out) {
    #pragma unroll
    for (int r = 0; r < N; ++r) out[r] = bias;
    #pragma unroll 2
    for (int k = 0; k < D; k += 4) {
        float w0 = wT[(k+0)*ldw + cidx], w1 = wT[(k+1)*ldw + cidx];
        float w2 = wT[(k+2)*ldw + cidx], w3 = wT[(k+3)*ldw + cidx];
        #pragma unroll
        for (int r = 0; r < N; ++r) {
            float4 hv = *reinterpret_cast<const float4*>(&hs[r][k]);
            out[r] = fmaf(hv.x, w0, out[r]); out[r] = fmaf(hv.y, w1, out[r]);
            out[r] = fmaf(hv.z, w2, out[r]); out[r] = fmaf(hv.w, w3, out[r]);
        }
    }
}

template<int N, int GPB>
__global__ __launch_bounds__(128)
void k1_kernel(const float* __restrict__ hin, const float* __restrict__ foldIn,
               float* __restrict__ t1, float* __restrict__ t2, float* __restrict__ acc,
               const float* __restrict__ gwT, const float* __restrict__ gb,
               const float* __restrict__ qwT, const float* __restrict__ qb,
               const float* __restrict__ owT, const float* __restrict__ ob) {
    __shared__ float h_s[N][DPAD], q_s[N][DPAD], k_s[N][DPAD], v_s[N][DPAD];
    __shared__ float sc_s[4][N][N + 1], m_s[D];
    const int c = threadIdx.x, wp = c >> 5, lane = c & 31;
    const float scIn = foldIn[c], shIn = foldIn[D + c];
    const float gbv = gb[c], obv = ob[c];
    const float qbq = qb[c], qbk = qb[D + c], qbv = qb[2*D + c];
    float s1 = 0.f, sq1 = 0.f, s2 = 0.f, sq2 = 0.f;
    for (int gi = 0; gi < GPB; ++gi) {
        const int g = blockIdx.x * GPB + gi;
        const float* hg = hin + (size_t)g * (N * D);
        float mv = 0.f;
        #pragma unroll
        for (int r = 0; r < N; ++r) {
            float v = fmaf(hg[r*D + c], scIn, shIn);
            h_s[r][c] = v; mv += v;
        }
        m_s[c] = mv * (1.f / N);
        __syncthreads();
        float gcnv = gbv;
        #pragma unroll 4
        for (int k = 0; k < D; ++k) gcnv = fmaf(m_s[k], gwT[k*D + c], gcnv);
        {
            float* t1g = t1 + (size_t)g * (N * D);
            #pragma unroll
            for (int r = 0; r < N; ++r) {
                float v = gcnv + h_s[r][c];
                t1g[r*D + c] = v; s1 += v; sq1 = fmaf(v, v, sq1);
            }
        }
        {
            float a[N];
            gemm128<N>(h_s, qwT, 384, c, qbq, a);
            #pragma unroll
            for (int r = 0; r < N; ++r) q_s[r][c] = a[r];
            gemm128<N>(h_s, qwT, 384, c + 128, qbk, a);
            #pragma unroll
            for (int r = 0; r < N; ++r) k_s[r][c] = a[r];
            gemm128<N>(h_s, qwT, 384, c + 256, qbv, a);
            #pragma unroll
            for (int r = 0; r < N; ++r) v_s[r][c] = a[r];
        }
        __syncthreads();
        {
            const float invs = 0.17677669529663687f;
            for (int p = lane; p < N * N; p += 32) {
                int r = p / N, s = p - r * N;
                float d0 = 0.f;
                #pragma unroll
                for (int d = 0; d < 32; d += 4) {
                    float4 qq = *reinterpret_cast<const float4*>(&q_s[r][wp*32 + d]);
                    float4 kk = *reinterpret_cast<const float4*>(&k_s[s][wp*32 + d]);
                    d0 = fmaf(qq.x, kk.x, d0); d0 = fmaf(qq.y, kk.y, d0);
                    d0 = fmaf(qq.z, kk.z, d0); d0 = fmaf(qq.w, kk.w, d0);
                }
                sc_s[wp][r][s] = d0 * invs;
            }
            __syncwarp();
            if (lane < N) {
                float mx = -1e30f;
                #pragma unroll
                for (int s = 0; s < N; ++s) mx = fmaxf(mx, sc_s[wp][lane][s]);
                float sum = 0.f;
                #pragma unroll
                for (int s = 0; s < N; ++s) { float e = __expf(sc_s[wp][lane][s] - mx); sc_s[wp][lane][s] = e; sum += e; }
                float inv = 1.f / sum;
                #pragma unroll
                for (int s = 0; s < N; ++s) sc_s[wp][lane][s] *= inv;
            }
            __syncwarp();
            #pragma unroll
            for (int r = 0; r < N; ++r) {
                float o = 0.f;
                #pragma unroll
                for (int s = 0; s < N; ++s) o = fmaf(sc_s[wp][r][s], v_s[s][wp*32 + lane], o);
                q_s[r][wp*32 + lane] = o;
            }
        }
        __syncthreads();
        {
            float a[N];
            gemm128<N>(q_s, owT, 128, c, obv, a);
            float* t2g = t2 + (size_t)g * (N * D);
            #pragma unroll
            for (int r = 0; r < N; ++r) {
                float v = a[r] + h_s[r][c];
                t2g[r*D + c] = v; s2 += v; sq2 = fmaf(v, v, sq2);
            }
        }
        __syncthreads();
    }
    atomicAdd(&acc[c], s1); atomicAdd(&acc[128 + c], sq1);
    atomicAdd(&acc[256 + c], s2); atomicAdd(&acc[384 + c], sq2);
}

template<int N, int GPB>
__global__ __launch_bounds__(128)
void k2_kernel(const float* __restrict__ t1, const float* __restrict__ t2,
               const float* __restrict__ fold1, const float* __restrict__ fold2,
               float* __restrict__ hout, float* __restrict__ acc,
               const float* __restrict__ w1T, const float* __restrict__ b1,
               const float* __restrict__ w2T, const float* __restrict__ b2) {
    __shared__ float o_s[N][DPAD], u_s[N][260];
    const int c = threadIdx.x;
    const float sc1 = fold1[c], sh1 = fold1[128 + c];
    const float sc2 = fold2[c], sh2 = fold2[128 + c];
    const float b1a = b1[c], b1b = b1[128 + c], b2a = b2[c];
    float s3 = 0.f, q3 = 0.f;
    for (int gi = 0; gi < GPB; ++gi) {
        const int g = blockIdx.x * GPB + gi;
        const float* t1g = t1 + (size_t)g * (N * D);
        const float* t2g = t2 + (size_t)g * (N * D);
        #pragma unroll
        for (int r = 0; r < N; ++r)
            o_s[r][c] = fmaf(t1g[r*D + c], sc1, sh1) + fmaf(t2g[r*D + c], sc2, sh2);
        __syncthreads();
        {
            float a0[N], a1[N];
            #pragma unroll
            for (int r = 0; r < N; ++r) { a0[r] = b1a; a1[r] = b1b; }
            #pragma unroll 2
            for (int k = 0; k < D; k += 4) {
                float wa0 = w1T[(k+0)*256 + c], wb0 = w1T[(k+0)*256 + 128 + c];
                float wa1 = w1T[(k+1)*256 + c], wb1 = w1T[(k+1)*256 + 128 + c];
                float wa2 = w1T[(k+2)*256 + c], wb2 = w1T[(k+2)*256 + 128 + c];
                float wa3 = w1T[(k+3)*256 + c], wb3 = w1T[(k+3)*256 + 128 + c];
                #pragma unroll
                for (int r = 0; r < N; ++r) {
                    float4 hv = *reinterpret_cast<const float4*>(&o_s[r][k]);
                    a0[r] = fmaf(hv.x, wa0, a0[r]);  a1[r] = fmaf(hv.x, wb0, a1[r]);
                    a0[r] = fmaf(hv.y, wa1, a0[r]);  a1[r] = fmaf(hv.y, wb1, a1[r]);
                    a0[r] = fmaf(hv.z, wa2, a0[r]);  a1[r] = fmaf(hv.z, wb2, a1[r]);
                    a0[r] = fmaf(hv.w, wa3, a0[r]);  a1[r] = fmaf(hv.w, wb3, a1[r]);
                }
            }
            #pragma unroll
            for (int r = 0; r < N; ++r) {
                u_s[r][c] = fmaxf(a0[r], 0.f); u_s[r][128 + c] = fmaxf(a1[r], 0.f);
            }
        }
        __syncthreads();
        {
            float a0[N];
            #pragma unroll
            for (int r = 0; r < N; ++r) a0[r] = b2a;
            #pragma unroll 2
            for (int j = 0; j < 256; j += 4) {
                float w0 = w2T[(j+0)*D + c], w1v = w2T[(j+1)*D + c];
                float w2v = w2T[(j+2)*D + c], w3 = w2T[(j+3)*D + c];
                #pragma unroll
                for (int r = 0; r < N; ++r) {
                    float4 uv = *reinterpret_cast<const float4*>(&u_s[r][j]);
                    a0[r] = fmaf(uv.x, w0, a0[r]); a0[r] = fmaf(uv.y, w1v, a0[r]);
                    a0[r] = fmaf(uv.z, w2v, a0[r]); a0[r] = fmaf(uv.w, w3, a0[r]);
                }
            }
            float* og = hout + (size_t)g * (N * D);
            #pragma unroll
            for (int r = 0; r < N; ++r) {
                float v = o_s[r][c] + a0[r];
                og[r*D + c] = v; s3 += v; q3 = fmaf(v, v, q3);
            }
        }
        __syncthreads();
    }
    atomicAdd(&acc[c], s3); atomicAdd(&acc[128 + c], q3);
}

extern "C" void kernel_launch(void* const* d_in, const int* in_sizes, int n_in,
                              void* d_out, int out_size) {
    const float* poses = (const float*)d_in[0];
    const float* emb_w = (const float*)d_in[1];
    const float* emb_b = (const float*)d_in[2];
    const float* cls_w = (const float*)d_in[3];
    const float* cls_b = (const float*)d_in[4];
    const float* PPj[12]; const float* PPi[12];
    for (int i = 0; i < 12; ++i) { PPj[i] = (const float*)d_in[5+i]; PPi[i] = (const float*)d_in[17+i]; }

    float *A, *Bb, *Cc, *A2, *B2, *C2, *acc, *fold, *wT; uint2* wf;
    cudaGetSymbolAddress((void**)&A,    g_A);
    cudaGetSymbolAddress((void**)&Bb,   g_B);
    cudaGetSymbolAddress((void**)&Cc,   g_C);
    cudaGetSymbolAddress((void**)&A2,   g_A2);
    cudaGetSymbolAddress((void**)&B2,   g_B2);
    cudaGetSymbolAddress((void**)&C2,   g_C2);
    cudaGetSymbolAddress((void**)&acc,  g_acc);
    cudaGetSymbolAddress((void**)&fold, g_fold);
    cudaGetSymbolAddress((void**)&wT,   g_wT);
    cudaGetSymbolAddress((void**)&wf,   g_wf);
    const float* foldId = fold + 18 * 256;

    cudaFuncSetAttribute(k1_s1, cudaFuncAttributeMaxDynamicSharedMemorySize, SM1);
    cudaFuncSetAttribute(k2_s1, cudaFuncAttributeMaxDynamicSharedMemorySize, SM2);

    init_kernel<<<18, 256>>>(acc, fold + 18 * 256);

    transpose_kernel<<<192, 256>>>(PPj[0], wT, 128, 128, 49152);
    for (int l = 0; l < 3; ++l) {
        prep_frag<<<48, 256>>>(PPj[2]  + l*49152, wf + l*32768,          48, 128, 12288);
        prep_frag<<<16, 256>>>(PPj[4]  + l*16384, wf + l*32768 + 12288,  16, 128, 4096);
        prep_frag<<<32, 256>>>(PPj[8]  + l*32768, wf + l*32768 + 16384,  32, 128, 8192);
        prep_frag<<<32, 256>>>(PPj[10] + l*32768, wf + l*32768 + 24576,  16, 256, 8192);
    }
    {
        float* wTs = wT + 442368;
        transpose_kernel<<<192, 256>>>(PPi[0],  wTs + 0,      128, 128, 49152);
        transpose_kernel<<<576, 256>>>(PPi[2],  wTs + 49152,  384, 128, 147456);
        transpose_kernel<<<192, 256>>>(PPi[4],  wTs + 196608, 128, 128, 49152);
        transpose_kernel<<<384, 256>>>(PPi[8],  wTs + 245760, 256, 128, 98304);
        transpose_kernel<<<384, 256>>>(PPi[10], wTs + 344064, 128, 256, 98304);
    }

    embed_kernel<<<182784, 256>>>(poses, emb_w, emb_b, A, 46792704);

    // stage 1 (tensor-core, 2 CTAs/SM)
    const float* foldPrev = foldId;
    for (int l = 0; l < 3; ++l) {
        float* accL = acc + l * 768;
        float* foldL = fold + l * 768;
        k1_s1<<<10752, 256, SM1>>>(A, foldPrev, Bb, Cc, accL,
                                   wT + l*16384, PPj[1] + l*128, PPj[3] + l*384, PPj[5] + l*128,
                                   wf + l*32768, wf + l*32768 + 12288);
        finalize_kernel<<<2, 128>>>(accL, 1.f/365568.f, PPj[6] + l*384, PPj[7] + l*384, foldL,
                                    PPj[6] + l*384 + 128, PPj[7] + l*384 + 128, foldL + 256);
        k2_s1<<<5376, 256, SM2>>>(A, Bb, Cc, foldPrev, foldL, foldL + 256, A, accL + 512,
                                  wf + l*32768 + 16384, PPj[9] + l*256,
                                  wf + l*32768 + 24576, PPj[11] + l*128);
        finalize_kernel<<<1, 128>>>(accL + 512, 1.f/365568.f, PPj[6] + l*384 + 256,
                                    PPj[7] + l*384 + 256, foldL + 512, nullptr, nullptr, nullptr);
        foldPrev = foldL + 512;
    }

    pool1_kernel<<<10752, 256>>>(A, foldPrev, A2, 2752512);

    // stage 2 (scalar)
    foldPrev = foldId;
    float* wTs = wT + 442368;
    for (int l = 0; l < 3; ++l) {
        float* accL = acc + 2304 + l * 768;
        float* foldL = fold + 2304 + l * 768;
        k1_kernel<12, 2><<<896, 128>>>(A2, foldPrev, B2, C2, accL,
                                       wTs + l*16384, PPi[1] + l*128, wTs + 49152 + l*49152,
                                       PPi[3] + l*384, wTs + 196608 + l*16384, PPi[5] + l*128);
        finalize_kernel<<<2, 128>>>(accL, 1.f/21504.f, PPi[6] + l*384, PPi[7] + l*384, foldL,
                                    PPi[6] + l*384 + 128, PPi[7] + l*384 + 128, foldL + 256);
        k2_kernel<12, 2><<<896, 128>>>(B2, C2, foldL, foldL + 256, A2, accL + 512,
                                       wTs + 245760 + l*32768, PPi[9] + l*256,
                                       wTs + 344064 + l*32768, PPi[11] + l*128);
        finalize_kernel<<<1, 128>>>(accL + 512, 1.f/21504.f, PPi[6] + l*384 + 256,
                                    PPi[7] + l*384 + 256, foldL + 512, nullptr, nullptr, nullptr);
        foldPrev = foldL + 512;
    }

    pool2_cls_kernel<<<256, 128>>>(A2, foldPrev, cls_w, cls_b, (float*)d_out);
}